// round 5
// baseline (speedup 1.0000x reference)
#include <cuda_runtime.h>

#define MAXN 100000
#define MAXE 600000
#define NG_GRAPHS 512
#define SCAN_B 1024

// Scratch (static device globals; allocation-free).
__device__ __align__(16) float g_t[MAXN * 128];
__device__ __align__(16) float g_h[MAXN * 128];
__device__ __align__(16) float g_whi[128 * 128 + 64 * 128];  // W2^T,W3^T hi (n-major)
__device__ __align__(16) float g_wlo[128 * 128 + 64 * 128];  // lo parts
__device__ __align__(16) float g_dis[MAXN];
__device__ __align__(16) int   g_cnt[MAXN];
__device__ __align__(16) int   g_offs[MAXN + 1];
__device__ __align__(16) int   g_cur[MAXN];
__device__ __align__(16) int   g_adj[MAXE];
__device__ __align__(16) int   g_bsum[128];
__device__ __align__(16) float g_sums[NG_GRAPHS * 64];
__device__ __align__(16) float g_gcnt[NG_GRAPHS];

__device__ __forceinline__ unsigned f2tf32(float x) {
    unsigned r;
    asm("cvt.rna.tf32.f32 %0, %1;" : "=r"(r) : "f"(x));
    return r;
}

// ---------------------------------------------------------------------------
// CSR build: count, scan, fill
// ---------------------------------------------------------------------------
__global__ void count_kernel(const int* __restrict__ dst, int* cnt, int E) {
    int i = blockIdx.x * blockDim.x + threadIdx.x;
    if (i < E) atomicAdd(&cnt[dst[i]], 1);
}

__global__ __launch_bounds__(SCAN_B) void scan_block_kernel(
    const int* __restrict__ cnt, int* offs, int* bsum, int N) {
    __shared__ int sh[SCAN_B];
    int t = threadIdx.x;
    int i = blockIdx.x * SCAN_B + t;
    int v = (i < N) ? cnt[i] : 0;
    sh[t] = v;
    __syncthreads();
#pragma unroll
    for (int off = 1; off < SCAN_B; off <<= 1) {
        int add = (t >= off) ? sh[t - off] : 0;
        __syncthreads();
        sh[t] += add;
        __syncthreads();
    }
    if (i < N) offs[i] = sh[t] - v;  // exclusive
    if (t == SCAN_B - 1) bsum[blockIdx.x] = sh[t];
}

__global__ void scan_top_kernel(int* bsum, int NB) {
    __shared__ int sh[128];
    int t = threadIdx.x;
    int v = (t < NB) ? bsum[t] : 0;
    sh[t] = v;
    __syncthreads();
#pragma unroll
    for (int off = 1; off < 128; off <<= 1) {
        int add = (t >= off) ? sh[t - off] : 0;
        __syncthreads();
        sh[t] += add;
        __syncthreads();
    }
    if (t < NB) bsum[t] = sh[t] - v;
}

__global__ void scan_add_kernel(int* offs, const int* __restrict__ bsum,
                                int* cur, const int* __restrict__ cnt,
                                float* dis, int N, int E) {
    int i = blockIdx.x * blockDim.x + threadIdx.x;
    if (i < N) {
        int o = offs[i] + bsum[i >> 10];
        offs[i] = o;
        cur[i] = o;
        dis[i] = rsqrtf((float)cnt[i] + 1.0f);  // +1 self loop
    }
    if (i == 0) offs[N] = E;
}

__global__ void fill_kernel(const int* __restrict__ src, const int* __restrict__ dst,
                            int* cur, int* adj, int E) {
    int i = blockIdx.x * blockDim.x + threadIdx.x;
    if (i < E) {
        int slot = atomicAdd(&cur[dst[i]], 1);
        adj[slot] = src[i];
    }
}

// ---------------------------------------------------------------------------
// prep: transpose W2 (128x128) and W3 (128x64) into n-major, split hi/lo tf32
// ---------------------------------------------------------------------------
__global__ void prep_wt_kernel(const float* __restrict__ W2, const float* __restrict__ W3,
                               float* whi, float* wlo) {
    int i = blockIdx.x * blockDim.x + threadIdx.x;
    float w;
    int o;
    if (i < 128 * 128) {
        int n = i >> 7, k = i & 127;
        w = W2[k * 128 + n];
        o = n * 128 + k;
    } else if (i < 128 * 128 + 64 * 128) {
        int j = i - 128 * 128;
        int n = j >> 7, k = j & 127;
        w = W3[k * 64 + n];
        o = 128 * 128 + n * 128 + k;
    } else {
        return;
    }
    float hi = __uint_as_float(f2tf32(w));
    whi[o] = hi;
    wlo[o] = __uint_as_float(f2tf32(w - hi));
}

// ---------------------------------------------------------------------------
// layer 1: t[n] = (x[n] @ W1) * dis[n],  K=3, F=128 (fp32)
// ---------------------------------------------------------------------------
__global__ __launch_bounds__(256) void layer1_kernel(
    const float* __restrict__ x, const float* __restrict__ W1,
    const float* __restrict__ dis, float* __restrict__ t, int N) {
    __shared__ float ws[3 * 128];
    for (int i = threadIdx.x; i < 384; i += blockDim.x) ws[i] = W1[i];
    __syncthreads();
    int idx = blockIdx.x * blockDim.x + threadIdx.x;
    int n = idx >> 5;
    int l = idx & 31;
    if (n >= N) return;
    float x0 = x[n * 3 + 0], x1 = x[n * 3 + 1], x2 = x[n * 3 + 2];
    float d = dis[n];
    int f = l * 4;
    float4 o;
    o.x = (x0 * ws[f + 0] + x1 * ws[128 + f + 0] + x2 * ws[256 + f + 0]) * d;
    o.y = (x0 * ws[f + 1] + x1 * ws[128 + f + 1] + x2 * ws[256 + f + 1]) * d;
    o.z = (x0 * ws[f + 2] + x1 * ws[128 + f + 2] + x2 * ws[256 + f + 2]) * d;
    o.w = (x0 * ws[f + 3] + x1 * ws[128 + f + 3] + x2 * ws[256 + f + 3]) * d;
    *(float4*)(t + (size_t)n * 128 + f) = o;
}

// ---------------------------------------------------------------------------
// tensor-core tf32x3 GEMM: out[n] = (A[n] @ W) * dis[n], fp32 in/out.
// mma.sync.m16n8k8.row.col.f32.tf32.tf32.f32, hi/lo split (3 MMAs).
// Tile: 128 nodes x F, 8 warps, warp = 16 rows. Whole K=128 in smem.
// ---------------------------------------------------------------------------
#define GLDA 132  // floats per smem row (128 + 4 pad -> conflict-free frags)

template <int F>
__global__ __launch_bounds__(256) void gemm_tf32_kernel(
    const float* __restrict__ A, const float* __restrict__ Whi,
    const float* __restrict__ Wlo, const float* __restrict__ dis,
    float* __restrict__ out, int N) {
    extern __shared__ float smf[];
    float* As = smf;                 // 128 x GLDA
    float* Bh = As + 128 * GLDA;     // F x GLDA
    float* Bl = Bh + F * GLDA;       // F x GLDA

    const int tid = threadIdx.x;
    const int warp = tid >> 5;
    const int lane = tid & 31;
    const int n0 = blockIdx.x * 128;

    // stage A: 128 rows x 128 floats
    for (int i = tid; i < 128 * 32; i += 256) {
        int r = i >> 5, c = i & 31;
        float4 v = make_float4(0.f, 0.f, 0.f, 0.f);
        int n = n0 + r;
        if (n < N) v = *(const float4*)(A + (size_t)n * 128 + c * 4);
        *(float4*)(As + r * GLDA + c * 4) = v;
    }
    // stage B hi/lo: F rows x 128 floats each
    for (int i = tid; i < F * 32; i += 256) {
        int r = i >> 5, c = i & 31;
        *(float4*)(Bh + r * GLDA + c * 4) = *(const float4*)(Whi + r * 128 + c * 4);
        *(float4*)(Bl + r * GLDA + c * 4) = *(const float4*)(Wlo + r * 128 + c * 4);
    }
    __syncthreads();

    constexpr int NT = F / 8;
    float acc[NT][4];
#pragma unroll
    for (int i = 0; i < NT; i++) {
        acc[i][0] = acc[i][1] = acc[i][2] = acc[i][3] = 0.f;
    }

    const int g = lane >> 2;   // 0..7
    const int tg = lane & 3;   // 0..3
    const float* arow0 = As + (warp * 16 + g) * GLDA + tg;
    const float* arow1 = arow0 + 8 * GLDA;

#pragma unroll
    for (int ks = 0; ks < 16; ks++) {
        const int k0 = ks * 8;
        float f0 = arow0[k0];
        float f1 = arow1[k0];
        float f2 = arow0[k0 + 4];
        float f3 = arow1[k0 + 4];
        unsigned ah0 = f2tf32(f0), ah1 = f2tf32(f1), ah2 = f2tf32(f2), ah3 = f2tf32(f3);
        unsigned al0 = f2tf32(f0 - __uint_as_float(ah0));
        unsigned al1 = f2tf32(f1 - __uint_as_float(ah1));
        unsigned al2 = f2tf32(f2 - __uint_as_float(ah2));
        unsigned al3 = f2tf32(f3 - __uint_as_float(ah3));
#pragma unroll
        for (int nt = 0; nt < NT; nt++) {
            const float* bhr = Bh + (nt * 8 + g) * GLDA + k0 + tg;
            const float* blr = Bl + (nt * 8 + g) * GLDA + k0 + tg;
            unsigned bh0 = __float_as_uint(bhr[0]);
            unsigned bh1 = __float_as_uint(bhr[4]);
            unsigned bl0 = __float_as_uint(blr[0]);
            unsigned bl1 = __float_as_uint(blr[4]);
            asm volatile(
                "mma.sync.aligned.m16n8k8.row.col.f32.tf32.tf32.f32 "
                "{%0,%1,%2,%3}, {%4,%5,%6,%7}, {%8,%9}, {%0,%1,%2,%3};"
                : "+f"(acc[nt][0]), "+f"(acc[nt][1]), "+f"(acc[nt][2]), "+f"(acc[nt][3])
                : "r"(ah0), "r"(ah1), "r"(ah2), "r"(ah3), "r"(bl0), "r"(bl1));
            asm volatile(
                "mma.sync.aligned.m16n8k8.row.col.f32.tf32.tf32.f32 "
                "{%0,%1,%2,%3}, {%4,%5,%6,%7}, {%8,%9}, {%0,%1,%2,%3};"
                : "+f"(acc[nt][0]), "+f"(acc[nt][1]), "+f"(acc[nt][2]), "+f"(acc[nt][3])
                : "r"(al0), "r"(al1), "r"(al2), "r"(al3), "r"(bh0), "r"(bh1));
            asm volatile(
                "mma.sync.aligned.m16n8k8.row.col.f32.tf32.tf32.f32 "
                "{%0,%1,%2,%3}, {%4,%5,%6,%7}, {%8,%9}, {%0,%1,%2,%3};"
                : "+f"(acc[nt][0]), "+f"(acc[nt][1]), "+f"(acc[nt][2]), "+f"(acc[nt][3])
                : "r"(ah0), "r"(ah1), "r"(ah2), "r"(ah3), "r"(bh0), "r"(bh1));
        }
    }

    // epilogue: c0,c1 = row g cols 2tg,2tg+1; c2,c3 = row g+8.
    int m0 = n0 + warp * 16 + g;
    int m1 = m0 + 8;
    float d0 = (m0 < N) ? dis[m0] : 0.f;
    float d1 = (m1 < N) ? dis[m1] : 0.f;
#pragma unroll
    for (int nt = 0; nt < NT; nt++) {
        if (m0 < N) {
            float2 o = make_float2(acc[nt][0] * d0, acc[nt][1] * d0);
            *(float2*)(out + (size_t)m0 * F + nt * 8 + tg * 2) = o;
        }
        if (m1 < N) {
            float2 o = make_float2(acc[nt][2] * d1, acc[nt][3] * d1);
            *(float2*)(out + (size_t)m1 * F + nt * 8 + tg * 2) = o;
        }
    }
}

// ---------------------------------------------------------------------------
// CSR gather + epilogue: h[d] = relu(dis[d]*(sum_{s in adj(d)} t[s] + t[d]) + b)
// One warp per dst node; fp32.
// ---------------------------------------------------------------------------
template <int F>
__global__ __launch_bounds__(256) void gather_kernel(
    const int* __restrict__ offs, const int* __restrict__ adj,
    const float* __restrict__ t, const float* __restrict__ dis,
    const float* __restrict__ b, float* __restrict__ h, int N) {
    int node = (blockIdx.x * 256 + threadIdx.x) >> 5;
    int lane = threadIdx.x & 31;
    if (node >= N) return;
    int beg = offs[node];
    int end = offs[node + 1];
    float d = dis[node];
    if constexpr (F == 128) {
        const float4* tv = (const float4*)t;
        float4 s0 = __ldg(&tv[(size_t)node * 32 + lane]);  // self loop
        float4 s1 = make_float4(0.f, 0.f, 0.f, 0.f);
        int e = beg;
        for (; e + 2 <= end; e += 2) {
            int a0 = __ldg(&adj[e]);
            int a1 = __ldg(&adj[e + 1]);
            float4 v0 = __ldg(&tv[(size_t)a0 * 32 + lane]);
            float4 v1 = __ldg(&tv[(size_t)a1 * 32 + lane]);
            s0.x += v0.x; s0.y += v0.y; s0.z += v0.z; s0.w += v0.w;
            s1.x += v1.x; s1.y += v1.y; s1.z += v1.z; s1.w += v1.w;
        }
        if (e < end) {
            int a = __ldg(&adj[e]);
            float4 v = __ldg(&tv[(size_t)a * 32 + lane]);
            s0.x += v.x; s0.y += v.y; s0.z += v.z; s0.w += v.w;
        }
        float4 bv = __ldg(&((const float4*)b)[lane]);
        float4 o;
        o.x = fmaxf(fmaf(s0.x + s1.x, d, bv.x), 0.f);
        o.y = fmaxf(fmaf(s0.y + s1.y, d, bv.y), 0.f);
        o.z = fmaxf(fmaf(s0.z + s1.z, d, bv.z), 0.f);
        o.w = fmaxf(fmaf(s0.w + s1.w, d, bv.w), 0.f);
        ((float4*)h)[(size_t)node * 32 + lane] = o;
    } else {
        const float2* tv = (const float2*)t;
        float2 s0 = __ldg(&tv[(size_t)node * 32 + lane]);
        float2 s1 = make_float2(0.f, 0.f);
        int e = beg;
        for (; e + 2 <= end; e += 2) {
            int a0 = __ldg(&adj[e]);
            int a1 = __ldg(&adj[e + 1]);
            float2 v0 = __ldg(&tv[(size_t)a0 * 32 + lane]);
            float2 v1 = __ldg(&tv[(size_t)a1 * 32 + lane]);
            s0.x += v0.x; s0.y += v0.y;
            s1.x += v1.x; s1.y += v1.y;
        }
        if (e < end) {
            int a = __ldg(&adj[e]);
            float2 v = __ldg(&tv[(size_t)a * 32 + lane]);
            s0.x += v.x; s0.y += v.y;
        }
        float2 bv = __ldg(&((const float2*)b)[lane]);
        float2 o;
        o.x = fmaxf(fmaf(s0.x + s1.x, d, bv.x), 0.f);
        o.y = fmaxf(fmaf(s0.y + s1.y, d, bv.y), 0.f);
        ((float2*)h)[(size_t)node * 32 + lane] = o;
    }
}

// ---------------------------------------------------------------------------
// pooling: batch sorted -> segmented reduction, atomic flush at boundaries
// ---------------------------------------------------------------------------
__global__ __launch_bounds__(64) void pool_kernel(
    const float* __restrict__ h, const int* __restrict__ batch,
    float* __restrict__ sums, float* __restrict__ cnt, int N) {
    int start = blockIdx.x * 256;
    int end = min(start + 256, N);
    int f = threadIdx.x;
    int g = batch[start];
    float s = 0.f, c = 0.f;
    for (int n = start; n < end; n++) {
        int bn = batch[n];
        if (bn != g) {
            atomicAdd(&sums[g * 64 + f], s);
            if (f == 0) atomicAdd(&cnt[g], c);
            s = 0.f; c = 0.f; g = bn;
        }
        s += h[(size_t)n * 64 + f];
        c += 1.f;
    }
    atomicAdd(&sums[g * 64 + f], s);
    if (f == 0) atomicAdd(&cnt[g], c);
}

__global__ void final_kernel(const float* __restrict__ sums, const float* __restrict__ cnt,
                             const float* __restrict__ Wl, const float* __restrict__ bl,
                             float* __restrict__ out) {
    int g = blockIdx.x * blockDim.x + threadIdx.x;
    if (g >= NG_GRAPHS) return;
    float c = fmaxf(cnt[g], 1.0f);
    float acc = 0.f;
#pragma unroll
    for (int f = 0; f < 64; f++) acc = fmaf(sums[g * 64 + f], Wl[f], acc);
    out[g] = acc / c + bl[0];
}

// ---------------------------------------------------------------------------
extern "C" void kernel_launch(void* const* d_in, const int* in_sizes, int n_in,
                              void* d_out, int out_size) {
    const float* x     = (const float*)d_in[0];
    const int*   ei    = (const int*)d_in[1];    // int32
    const int*   batch = (const int*)d_in[2];    // int32
    const float* W1 = (const float*)d_in[3];
    const float* b1 = (const float*)d_in[4];
    const float* W2 = (const float*)d_in[5];
    const float* b2 = (const float*)d_in[6];
    const float* W3 = (const float*)d_in[7];
    const float* b3 = (const float*)d_in[8];
    const float* Wl = (const float*)d_in[9];
    const float* bl = (const float*)d_in[10];
    float* out = (float*)d_out;

    const int N = in_sizes[0] / 3;
    const int E = in_sizes[1] / 2;
    const int* srcp = ei;
    const int* dstp = ei + E;

    float *t, *h, *whi, *wlo, *dis, *sums, *gcnt;
    int *cnt, *offs, *cur, *adj, *bsum;
    cudaGetSymbolAddress((void**)&t, g_t);
    cudaGetSymbolAddress((void**)&h, g_h);
    cudaGetSymbolAddress((void**)&whi, g_whi);
    cudaGetSymbolAddress((void**)&wlo, g_wlo);
    cudaGetSymbolAddress((void**)&dis, g_dis);
    cudaGetSymbolAddress((void**)&cnt, g_cnt);
    cudaGetSymbolAddress((void**)&offs, g_offs);
    cudaGetSymbolAddress((void**)&cur, g_cur);
    cudaGetSymbolAddress((void**)&adj, g_adj);
    cudaGetSymbolAddress((void**)&bsum, g_bsum);
    cudaGetSymbolAddress((void**)&sums, g_sums);
    cudaGetSymbolAddress((void**)&gcnt, g_gcnt);

    const int SMEM128 = (128 + 2 * 128) * GLDA * 4;
    const int SMEM64  = (128 + 2 * 64) * GLDA * 4;
    cudaFuncSetAttribute(gemm_tf32_kernel<128>,
                         cudaFuncAttributeMaxDynamicSharedMemorySize, SMEM128);
    cudaFuncSetAttribute(gemm_tf32_kernel<64>,
                         cudaFuncAttributeMaxDynamicSharedMemorySize, SMEM64);

    const int nB = (N + 255) / 256;
    const int eB = (E + 255) / 256;
    const int NB_SCAN = (N + SCAN_B - 1) / SCAN_B;
    const int wB = (N * 32 + 255) / 256;      // warp-per-node grids
    const int gB = (N + 127) / 128;           // gemm grids

    // --- CSR build (once, reused for all 3 layers) ---
    cudaMemsetAsync(cnt, 0, (size_t)N * sizeof(int), 0);
    count_kernel<<<eB, 256>>>(dstp, cnt, E);
    scan_block_kernel<<<NB_SCAN, SCAN_B>>>(cnt, offs, bsum, N);
    scan_top_kernel<<<1, 128>>>(bsum, NB_SCAN);
    scan_add_kernel<<<nB, 256>>>(offs, bsum, cur, cnt, dis, N, E);
    fill_kernel<<<eB, 256>>>(srcp, dstp, cur, adj, E);
    prep_wt_kernel<<<(128 * 128 + 64 * 128 + 255) / 256, 256>>>(W2, W3, whi, wlo);

    // --- layer 1 (3 -> 128) ---
    layer1_kernel<<<wB, 256>>>(x, W1, dis, t, N);
    gather_kernel<128><<<wB, 256>>>(offs, adj, t, dis, b1, h, N);

    // --- layer 2 (128 -> 128) ---
    gemm_tf32_kernel<128><<<gB, 256, SMEM128>>>(h, whi, wlo, dis, t, N);
    gather_kernel<128><<<wB, 256>>>(offs, adj, t, dis, b2, h, N);

    // --- layer 3 (128 -> 64) ---
    gemm_tf32_kernel<64><<<gB, 256, SMEM64>>>(h, whi + 128 * 128, wlo + 128 * 128, dis, t, N);
    gather_kernel<64><<<wB, 256>>>(offs, adj, t, dis, b3, h, N);

    // --- pooling + final linear ---
    cudaMemsetAsync(sums, 0, NG_GRAPHS * 64 * sizeof(float), 0);
    cudaMemsetAsync(gcnt, 0, NG_GRAPHS * sizeof(float), 0);
    pool_kernel<<<(N + 255) / 256, 64>>>(h, batch, sums, gcnt, N);
    final_kernel<<<2, 256>>>(sums, gcnt, Wl, bl, out);
}

// round 7
// speedup vs baseline: 1.4072x; 1.4072x over previous
#include <cuda_runtime.h>
#include <cuda_bf16.h>
#include <cstdint>

#define MAXN 100000
#define MAXE 600000
#define NG_GRAPHS 512
#define SCAN_B 1024

// Scratch (static device globals; allocation-free).
__device__ __align__(16) float g_t[MAXN * 128];
__device__ __align__(16) float g_h[MAXN * 128];
__device__ __align__(16) __nv_bfloat16 g_bh2[128 * 128];  // W2^T hi (n-major [n][k])
__device__ __align__(16) __nv_bfloat16 g_bl2[128 * 128];  // W2^T lo
__device__ __align__(16) __nv_bfloat16 g_bh3[64 * 128];   // W3^T hi
__device__ __align__(16) __nv_bfloat16 g_bl3[64 * 128];   // W3^T lo
__device__ __align__(16) float g_dis[MAXN];
__device__ __align__(16) int   g_cnt[MAXN];
__device__ __align__(16) int   g_offs[MAXN + 1];
__device__ __align__(16) int   g_cur[MAXN];
__device__ __align__(16) int   g_adj[MAXE];
__device__ __align__(16) int   g_bsum[128];
__device__ __align__(16) float g_sums[NG_GRAPHS * 64];
__device__ __align__(16) float g_gcnt[NG_GRAPHS];

// ---------------------------------------------------------------------------
// CSR build: count, scan, fill
// ---------------------------------------------------------------------------
__global__ void count_kernel(const int* __restrict__ dst, int* cnt, int E) {
    int i = blockIdx.x * blockDim.x + threadIdx.x;
    if (i < E) atomicAdd(&cnt[dst[i]], 1);
}

__global__ __launch_bounds__(SCAN_B) void scan_block_kernel(
    const int* __restrict__ cnt, int* offs, int* bsum, int N) {
    __shared__ int sh[SCAN_B];
    int t = threadIdx.x;
    int i = blockIdx.x * SCAN_B + t;
    int v = (i < N) ? cnt[i] : 0;
    sh[t] = v;
    __syncthreads();
#pragma unroll
    for (int off = 1; off < SCAN_B; off <<= 1) {
        int add = (t >= off) ? sh[t - off] : 0;
        __syncthreads();
        sh[t] += add;
        __syncthreads();
    }
    if (i < N) offs[i] = sh[t] - v;  // exclusive
    if (t == SCAN_B - 1) bsum[blockIdx.x] = sh[t];
}

__global__ void scan_top_kernel(int* bsum, int NB) {
    __shared__ int sh[128];
    int t = threadIdx.x;
    int v = (t < NB) ? bsum[t] : 0;
    sh[t] = v;
    __syncthreads();
#pragma unroll
    for (int off = 1; off < 128; off <<= 1) {
        int add = (t >= off) ? sh[t - off] : 0;
        __syncthreads();
        sh[t] += add;
        __syncthreads();
    }
    if (t < NB) bsum[t] = sh[t] - v;
}

__global__ void scan_add_kernel(int* offs, const int* __restrict__ bsum,
                                int* cur, const int* __restrict__ cnt,
                                float* dis, int N, int E) {
    int i = blockIdx.x * blockDim.x + threadIdx.x;
    if (i < N) {
        int o = offs[i] + bsum[i >> 10];
        offs[i] = o;
        cur[i] = o;
        dis[i] = rsqrtf((float)cnt[i] + 1.0f);  // +1 self loop
    }
    if (i == 0) offs[N] = E;
}

__global__ void fill_kernel(const int* __restrict__ src, const int* __restrict__ dst,
                            int* cur, int* adj, int E) {
    int i = blockIdx.x * blockDim.x + threadIdx.x;
    if (i < E) {
        int slot = atomicAdd(&cur[dst[i]], 1);
        adj[slot] = src[i];
    }
}

// ---------------------------------------------------------------------------
// prep: W2 (128x128) / W3 (128x64) -> transposed n-major [n][k], bf16 hi/lo
// ---------------------------------------------------------------------------
__global__ void prep_b_kernel(const float* __restrict__ W2, const float* __restrict__ W3,
                              __nv_bfloat16* bh2, __nv_bfloat16* bl2,
                              __nv_bfloat16* bh3, __nv_bfloat16* bl3) {
    int i = blockIdx.x * blockDim.x + threadIdx.x;
    if (i < 128 * 128) {
        int n = i >> 7, k = i & 127;
        float w = W2[k * 128 + n];
        __nv_bfloat16 hi = __float2bfloat16_rn(w);
        __nv_bfloat16 lo = __float2bfloat16_rn(w - __bfloat162float(hi));
        bh2[n * 128 + k] = hi;
        bl2[n * 128 + k] = lo;
    } else if (i < 128 * 128 + 64 * 128) {
        int j = i - 128 * 128;
        int n = j >> 7, k = j & 127;
        float w = W3[k * 64 + n];
        __nv_bfloat16 hi = __float2bfloat16_rn(w);
        __nv_bfloat16 lo = __float2bfloat16_rn(w - __bfloat162float(hi));
        bh3[n * 128 + k] = hi;
        bl3[n * 128 + k] = lo;
    }
}

// ---------------------------------------------------------------------------
// layer 1: t[n] = (x[n] @ W1) * dis[n],  K=3, F=128 (fp32)
// ---------------------------------------------------------------------------
__global__ __launch_bounds__(256) void layer1_kernel(
    const float* __restrict__ x, const float* __restrict__ W1,
    const float* __restrict__ dis, float* __restrict__ t, int N) {
    __shared__ float ws[3 * 128];
    for (int i = threadIdx.x; i < 384; i += blockDim.x) ws[i] = W1[i];
    __syncthreads();
    int idx = blockIdx.x * blockDim.x + threadIdx.x;
    int n = idx >> 5;
    int l = idx & 31;
    if (n >= N) return;
    float x0 = x[n * 3 + 0], x1 = x[n * 3 + 1], x2 = x[n * 3 + 2];
    float d = dis[n];
    int f = l * 4;
    float4 o;
    o.x = (x0 * ws[f + 0] + x1 * ws[128 + f + 0] + x2 * ws[256 + f + 0]) * d;
    o.y = (x0 * ws[f + 1] + x1 * ws[128 + f + 1] + x2 * ws[256 + f + 1]) * d;
    o.z = (x0 * ws[f + 2] + x1 * ws[128 + f + 2] + x2 * ws[256 + f + 2]) * d;
    o.w = (x0 * ws[f + 3] + x1 * ws[128 + f + 3] + x2 * ws[256 + f + 3]) * d;
    *(float4*)(t + (size_t)n * 128 + f) = o;
}

// ---------------------------------------------------------------------------
// bf16x3 tensor-core GEMM via mma.sync.m16n8k16 (legacy HMMA, sm_103-safe):
//   out[n] = (A[n] @ W) * dis[n],  D = Ahi*Bhi + Ahi*Blo + Alo*Bhi, fp32 accum.
// Block = 256 thr (8 warps), tile = 128 rows x F. K staged in 2 chunks of 64.
// smem rows padded to 72 halfs -> conflict-free fragment LDS.
// ---------------------------------------------------------------------------
#define LDH 72  // halfs per smem row (64 + 8 pad)

template <int F>
__global__ __launch_bounds__(256) void gemm_mma_kernel(
    const float* __restrict__ A, const __nv_bfloat16* __restrict__ Bhg,
    const __nv_bfloat16* __restrict__ Blg, const float* __restrict__ dis,
    float* __restrict__ out, int N) {
    extern __shared__ __align__(16) __nv_bfloat16 smh[];
    __nv_bfloat16* Ah = smh;             // 128 x LDH
    __nv_bfloat16* Al = Ah + 128 * LDH;  // 128 x LDH
    __nv_bfloat16* Bh = Al + 128 * LDH;  // F x LDH
    __nv_bfloat16* Bl = Bh + F * LDH;    // F x LDH

    const int tid = threadIdx.x;
    const int warp = tid >> 5;
    const int lane = tid & 31;
    const int g = lane >> 2;   // 0..7
    const int tg = lane & 3;   // 0..3
    const int n0 = blockIdx.x * 128;

    constexpr int NT = F / 8;
    float acc[NT][4];
#pragma unroll
    for (int i = 0; i < NT; i++) {
        acc[i][0] = acc[i][1] = acc[i][2] = acc[i][3] = 0.f;
    }

    for (int kc = 0; kc < 128; kc += 64) {
        __syncthreads();  // protect smem from previous chunk's readers
        // stage A chunk [128 x 64] with bf16 hi/lo split
        for (int i = tid; i < 128 * 16; i += 256) {
            int r = i >> 4, c4 = i & 15;
            float4 v = make_float4(0.f, 0.f, 0.f, 0.f);
            int n = n0 + r;
            if (n < N) v = *(const float4*)(A + (size_t)n * 128 + kc + c4 * 4);
            __nv_bfloat16 h0 = __float2bfloat16_rn(v.x);
            __nv_bfloat16 h1 = __float2bfloat16_rn(v.y);
            __nv_bfloat16 h2 = __float2bfloat16_rn(v.z);
            __nv_bfloat16 h3 = __float2bfloat16_rn(v.w);
            __nv_bfloat162 hp0 = {h0, h1}, hp1 = {h2, h3};
            __nv_bfloat162 lp0 = {__float2bfloat16_rn(v.x - __bfloat162float(h0)),
                                  __float2bfloat16_rn(v.y - __bfloat162float(h1))};
            __nv_bfloat162 lp1 = {__float2bfloat16_rn(v.z - __bfloat162float(h2)),
                                  __float2bfloat16_rn(v.w - __bfloat162float(h3))};
            uint2 hu, lu;
            hu.x = *(uint32_t*)&hp0; hu.y = *(uint32_t*)&hp1;
            lu.x = *(uint32_t*)&lp0; lu.y = *(uint32_t*)&lp1;
            *(uint2*)(Ah + r * LDH + c4 * 4) = hu;
            *(uint2*)(Al + r * LDH + c4 * 4) = lu;
        }
        // stage B chunk [F x 64] (already bf16 hi/lo in global, n-major)
        for (int i = tid; i < F * 8; i += 256) {
            int r = i >> 3, c8 = i & 7;
            *(uint4*)(Bh + r * LDH + c8 * 8) = *(const uint4*)(Bhg + r * 128 + kc + c8 * 8);
            *(uint4*)(Bl + r * LDH + c8 * 8) = *(const uint4*)(Blg + r * 128 + kc + c8 * 8);
        }
        __syncthreads();

        const __nv_bfloat16* ar0 = Ah + (warp * 16 + g) * LDH + 2 * tg;
        const __nv_bfloat16* al0 = Al + (warp * 16 + g) * LDH + 2 * tg;
#pragma unroll
        for (int ks = 0; ks < 4; ks++) {
            const int ko = ks * 16;
            uint32_t ah0 = *(const uint32_t*)(ar0 + ko);
            uint32_t ah1 = *(const uint32_t*)(ar0 + 8 * LDH + ko);
            uint32_t ah2 = *(const uint32_t*)(ar0 + ko + 8);
            uint32_t ah3 = *(const uint32_t*)(ar0 + 8 * LDH + ko + 8);
            uint32_t aw0 = *(const uint32_t*)(al0 + ko);
            uint32_t aw1 = *(const uint32_t*)(al0 + 8 * LDH + ko);
            uint32_t aw2 = *(const uint32_t*)(al0 + ko + 8);
            uint32_t aw3 = *(const uint32_t*)(al0 + 8 * LDH + ko + 8);
#pragma unroll
            for (int nt = 0; nt < NT; nt++) {
                const __nv_bfloat16* bhr = Bh + (nt * 8 + g) * LDH + 2 * tg + ko;
                const __nv_bfloat16* blr = Bl + (nt * 8 + g) * LDH + 2 * tg + ko;
                uint32_t bh0 = *(const uint32_t*)bhr;
                uint32_t bh1 = *(const uint32_t*)(bhr + 8);
                uint32_t bl0 = *(const uint32_t*)blr;
                uint32_t bl1 = *(const uint32_t*)(blr + 8);
                asm volatile(
                    "mma.sync.aligned.m16n8k16.row.col.f32.bf16.bf16.f32 "
                    "{%0,%1,%2,%3}, {%4,%5,%6,%7}, {%8,%9}, {%0,%1,%2,%3};"
                    : "+f"(acc[nt][0]), "+f"(acc[nt][1]), "+f"(acc[nt][2]), "+f"(acc[nt][3])
                    : "r"(ah0), "r"(ah1), "r"(ah2), "r"(ah3), "r"(bh0), "r"(bh1));
                asm volatile(
                    "mma.sync.aligned.m16n8k16.row.col.f32.bf16.bf16.f32 "
                    "{%0,%1,%2,%3}, {%4,%5,%6,%7}, {%8,%9}, {%0,%1,%2,%3};"
                    : "+f"(acc[nt][0]), "+f"(acc[nt][1]), "+f"(acc[nt][2]), "+f"(acc[nt][3])
                    : "r"(aw0), "r"(aw1), "r"(aw2), "r"(aw3), "r"(bh0), "r"(bh1));
                asm volatile(
                    "mma.sync.aligned.m16n8k16.row.col.f32.bf16.bf16.f32 "
                    "{%0,%1,%2,%3}, {%4,%5,%6,%7}, {%8,%9}, {%0,%1,%2,%3};"
                    : "+f"(acc[nt][0]), "+f"(acc[nt][1]), "+f"(acc[nt][2]), "+f"(acc[nt][3])
                    : "r"(ah0), "r"(ah1), "r"(ah2), "r"(ah3), "r"(bl0), "r"(bl1));
            }
        }
    }

    // epilogue: c0,c1 = row g cols 2tg,2tg+1; c2,c3 = row g+8.
    int m0 = n0 + warp * 16 + g;
    int m1 = m0 + 8;
    float d0 = (m0 < N) ? dis[m0] : 0.f;
    float d1 = (m1 < N) ? dis[m1] : 0.f;
#pragma unroll
    for (int nt = 0; nt < NT; nt++) {
        if (m0 < N) {
            float2 o = make_float2(acc[nt][0] * d0, acc[nt][1] * d0);
            *(float2*)(out + (size_t)m0 * F + nt * 8 + tg * 2) = o;
        }
        if (m1 < N) {
            float2 o = make_float2(acc[nt][2] * d1, acc[nt][3] * d1);
            *(float2*)(out + (size_t)m1 * F + nt * 8 + tg * 2) = o;
        }
    }
}

// ---------------------------------------------------------------------------
// CSR gather + epilogue: h[d] = relu(dis[d]*(sum_{s in adj(d)} t[s] + t[d]) + b)
// One warp per dst node; fp32.
// ---------------------------------------------------------------------------
template <int F>
__global__ __launch_bounds__(256) void gather_kernel(
    const int* __restrict__ offs, const int* __restrict__ adj,
    const float* __restrict__ t, const float* __restrict__ dis,
    const float* __restrict__ b, float* __restrict__ h, int N) {
    int node = (blockIdx.x * 256 + threadIdx.x) >> 5;
    int lane = threadIdx.x & 31;
    if (node >= N) return;
    int beg = offs[node];
    int end = offs[node + 1];
    float d = dis[node];
    if constexpr (F == 128) {
        const float4* tv = (const float4*)t;
        float4 s0 = __ldg(&tv[(size_t)node * 32 + lane]);  // self loop
        float4 s1 = make_float4(0.f, 0.f, 0.f, 0.f);
        int e = beg;
        for (; e + 2 <= end; e += 2) {
            int a0 = __ldg(&adj[e]);
            int a1 = __ldg(&adj[e + 1]);
            float4 v0 = __ldg(&tv[(size_t)a0 * 32 + lane]);
            float4 v1 = __ldg(&tv[(size_t)a1 * 32 + lane]);
            s0.x += v0.x; s0.y += v0.y; s0.z += v0.z; s0.w += v0.w;
            s1.x += v1.x; s1.y += v1.y; s1.z += v1.z; s1.w += v1.w;
        }
        if (e < end) {
            int a = __ldg(&adj[e]);
            float4 v = __ldg(&tv[(size_t)a * 32 + lane]);
            s0.x += v.x; s0.y += v.y; s0.z += v.z; s0.w += v.w;
        }
        float4 bv = __ldg(&((const float4*)b)[lane]);
        float4 o;
        o.x = fmaxf(fmaf(s0.x + s1.x, d, bv.x), 0.f);
        o.y = fmaxf(fmaf(s0.y + s1.y, d, bv.y), 0.f);
        o.z = fmaxf(fmaf(s0.z + s1.z, d, bv.z), 0.f);
        o.w = fmaxf(fmaf(s0.w + s1.w, d, bv.w), 0.f);
        ((float4*)h)[(size_t)node * 32 + lane] = o;
    } else {
        const float2* tv = (const float2*)t;
        float2 s0 = __ldg(&tv[(size_t)node * 32 + lane]);
        float2 s1 = make_float2(0.f, 0.f);
        int e = beg;
        for (; e + 2 <= end; e += 2) {
            int a0 = __ldg(&adj[e]);
            int a1 = __ldg(&adj[e + 1]);
            float2 v0 = __ldg(&tv[(size_t)a0 * 32 + lane]);
            float2 v1 = __ldg(&tv[(size_t)a1 * 32 + lane]);
            s0.x += v0.x; s0.y += v0.y;
            s1.x += v1.x; s1.y += v1.y;
        }
        if (e < end) {
            int a = __ldg(&adj[e]);
            float2 v = __ldg(&tv[(size_t)a * 32 + lane]);
            s0.x += v.x; s0.y += v.y;
        }
        float2 bv = __ldg(&((const float2*)b)[lane]);
        float2 o;
        o.x = fmaxf(fmaf(s0.x + s1.x, d, bv.x), 0.f);
        o.y = fmaxf(fmaf(s0.y + s1.y, d, bv.y), 0.f);
        ((float2*)h)[(size_t)node * 32 + lane] = o;
    }
}

// ---------------------------------------------------------------------------
// pooling: batch sorted -> segmented reduction, atomic flush at boundaries
// ---------------------------------------------------------------------------
__global__ __launch_bounds__(64) void pool_kernel(
    const float* __restrict__ h, const int* __restrict__ batch,
    float* __restrict__ sums, float* __restrict__ cnt, int N) {
    int start = blockIdx.x * 256;
    int end = min(start + 256, N);
    int f = threadIdx.x;
    int g = batch[start];
    float s = 0.f, c = 0.f;
    for (int n = start; n < end; n++) {
        int bn = batch[n];
        if (bn != g) {
            atomicAdd(&sums[g * 64 + f], s);
            if (f == 0) atomicAdd(&cnt[g], c);
            s = 0.f; c = 0.f; g = bn;
        }
        s += h[(size_t)n * 64 + f];
        c += 1.f;
    }
    atomicAdd(&sums[g * 64 + f], s);
    if (f == 0) atomicAdd(&cnt[g], c);
}

__global__ void final_kernel(const float* __restrict__ sums, const float* __restrict__ cnt,
                             const float* __restrict__ Wl, const float* __restrict__ bl,
                             float* __restrict__ out) {
    int g = blockIdx.x * blockDim.x + threadIdx.x;
    if (g >= NG_GRAPHS) return;
    float c = fmaxf(cnt[g], 1.0f);
    float acc = 0.f;
#pragma unroll
    for (int f = 0; f < 64; f++) acc = fmaf(sums[g * 64 + f], Wl[f], acc);
    out[g] = acc / c + bl[0];
}

// ---------------------------------------------------------------------------
extern "C" void kernel_launch(void* const* d_in, const int* in_sizes, int n_in,
                              void* d_out, int out_size) {
    const float* x     = (const float*)d_in[0];
    const int*   ei    = (const int*)d_in[1];    // int32
    const int*   batch = (const int*)d_in[2];    // int32
    const float* W1 = (const float*)d_in[3];
    const float* b1 = (const float*)d_in[4];
    const float* W2 = (const float*)d_in[5];
    const float* b2 = (const float*)d_in[6];
    const float* W3 = (const float*)d_in[7];
    const float* b3 = (const float*)d_in[8];
    const float* Wl = (const float*)d_in[9];
    const float* bl = (const float*)d_in[10];
    float* out = (float*)d_out;

    const int N = in_sizes[0] / 3;
    const int E = in_sizes[1] / 2;
    const int* srcp = ei;
    const int* dstp = ei + E;

    float *t, *h, *dis, *sums, *gcnt;
    __nv_bfloat16 *bh2, *bl2, *bh3, *bl3;
    int *cnt, *offs, *cur, *adj, *bsum;
    cudaGetSymbolAddress((void**)&t, g_t);
    cudaGetSymbolAddress((void**)&h, g_h);
    cudaGetSymbolAddress((void**)&bh2, g_bh2);
    cudaGetSymbolAddress((void**)&bl2, g_bl2);
    cudaGetSymbolAddress((void**)&bh3, g_bh3);
    cudaGetSymbolAddress((void**)&bl3, g_bl3);
    cudaGetSymbolAddress((void**)&dis, g_dis);
    cudaGetSymbolAddress((void**)&cnt, g_cnt);
    cudaGetSymbolAddress((void**)&offs, g_offs);
    cudaGetSymbolAddress((void**)&cur, g_cur);
    cudaGetSymbolAddress((void**)&adj, g_adj);
    cudaGetSymbolAddress((void**)&bsum, g_bsum);
    cudaGetSymbolAddress((void**)&sums, g_sums);
    cudaGetSymbolAddress((void**)&gcnt, g_gcnt);

    // smem: (128 A rows hi+lo + F B rows hi+lo) x LDH halfs
    const int SMEM128 = (2 * 128 + 2 * 128) * LDH * 2;  // 73,728 B
    const int SMEM64  = (2 * 128 + 2 * 64) * LDH * 2;   // 55,296 B
    cudaFuncSetAttribute(gemm_mma_kernel<128>,
                         cudaFuncAttributeMaxDynamicSharedMemorySize, SMEM128);
    cudaFuncSetAttribute(gemm_mma_kernel<64>,
                         cudaFuncAttributeMaxDynamicSharedMemorySize, SMEM64);

    const int nB = (N + 255) / 256;
    const int eB = (E + 255) / 256;
    const int NB_SCAN = (N + SCAN_B - 1) / SCAN_B;
    const int wB = (N * 32 + 255) / 256;      // warp-per-node grids
    const int gB = (N + 127) / 128;           // gemm grids

    // --- CSR build (once, reused for all 3 layers) ---
    cudaMemsetAsync(cnt, 0, (size_t)N * sizeof(int), 0);
    count_kernel<<<eB, 256>>>(dstp, cnt, E);
    scan_block_kernel<<<NB_SCAN, SCAN_B>>>(cnt, offs, bsum, N);
    scan_top_kernel<<<1, 128>>>(bsum, NB_SCAN);
    scan_add_kernel<<<nB, 256>>>(offs, bsum, cur, cnt, dis, N, E);
    fill_kernel<<<eB, 256>>>(srcp, dstp, cur, adj, E);
    prep_b_kernel<<<(128 * 128 + 64 * 128 + 255) / 256, 256>>>(W2, W3, bh2, bl2, bh3, bl3);

    // --- layer 1 (3 -> 128) ---
    layer1_kernel<<<wB, 256>>>(x, W1, dis, t, N);
    gather_kernel<128><<<wB, 256>>>(offs, adj, t, dis, b1, h, N);

    // --- layer 2 (128 -> 128) ---
    gemm_mma_kernel<128><<<gB, 256, SMEM128>>>(h, bh2, bl2, dis, t, N);
    gather_kernel<128><<<wB, 256>>>(offs, adj, t, dis, b2, h, N);

    // --- layer 3 (128 -> 64) ---
    gemm_mma_kernel<64><<<gB, 256, SMEM64>>>(h, bh3, bl3, dis, t, N);
    gather_kernel<64><<<wB, 256>>>(offs, adj, t, dis, b3, h, N);

    // --- pooling + final linear ---
    cudaMemsetAsync(sums, 0, NG_GRAPHS * 64 * sizeof(float), 0);
    cudaMemsetAsync(gcnt, 0, NG_GRAPHS * sizeof(float), 0);
    pool_kernel<<<(N + 255) / 256, 64>>>(h, batch, sums, gcnt, N);
    final_kernel<<<2, 256>>>(sums, gcnt, Wl, bl, out);
}

// round 8
// speedup vs baseline: 1.6106x; 1.1445x over previous
#include <cuda_runtime.h>
#include <cuda_bf16.h>
#include <cstdint>

#define MAXN 100000
#define MAXE 600000
#define NG_GRAPHS 512
#define SCAN_B 1024

// Scratch (static device globals; allocation-free).
__device__ __align__(16) float g_t[MAXN * 128];
__device__ __align__(16) float g_h[MAXN * 128];
__device__ __align__(16) float g_xd[MAXN * 4];   // x * dis, padded float4
__device__ __align__(16) float g_z[MAXN * 4];    // 3-dim aggregated, padded
__device__ __align__(16) __nv_bfloat16 g_bh2[128 * 128];  // W2^T hi (n-major [n][k])
__device__ __align__(16) __nv_bfloat16 g_bl2[128 * 128];  // W2^T lo
__device__ __align__(16) __nv_bfloat16 g_bh3[64 * 128];   // W3^T hi
__device__ __align__(16) __nv_bfloat16 g_bl3[64 * 128];   // W3^T lo
__device__ __align__(16) float g_dis[MAXN];
__device__ __align__(16) int   g_cnt[MAXN];
__device__ __align__(16) int   g_offs[MAXN + 1];
__device__ __align__(16) int   g_cur[MAXN];
__device__ __align__(16) int   g_adj[MAXE];
__device__ __align__(16) int   g_bsum[128];
__device__ __align__(16) float g_sums[NG_GRAPHS * 64];
__device__ __align__(16) float g_gcnt[NG_GRAPHS];

// ---------------------------------------------------------------------------
// CSR build: count, scan, fill
// ---------------------------------------------------------------------------
__global__ void count_kernel(const int* __restrict__ dst, int* cnt, int E) {
    int i = blockIdx.x * blockDim.x + threadIdx.x;
    if (i < E) atomicAdd(&cnt[dst[i]], 1);
}

__global__ __launch_bounds__(SCAN_B) void scan_block_kernel(
    const int* __restrict__ cnt, int* offs, int* bsum, int N) {
    __shared__ int sh[SCAN_B];
    int t = threadIdx.x;
    int i = blockIdx.x * SCAN_B + t;
    int v = (i < N) ? cnt[i] : 0;
    sh[t] = v;
    __syncthreads();
#pragma unroll
    for (int off = 1; off < SCAN_B; off <<= 1) {
        int add = (t >= off) ? sh[t - off] : 0;
        __syncthreads();
        sh[t] += add;
        __syncthreads();
    }
    if (i < N) offs[i] = sh[t] - v;  // exclusive
    if (t == SCAN_B - 1) bsum[blockIdx.x] = sh[t];
}

__global__ void scan_top_kernel(int* bsum, int NB) {
    __shared__ int sh[128];
    int t = threadIdx.x;
    int v = (t < NB) ? bsum[t] : 0;
    sh[t] = v;
    __syncthreads();
#pragma unroll
    for (int off = 1; off < 128; off <<= 1) {
        int add = (t >= off) ? sh[t - off] : 0;
        __syncthreads();
        sh[t] += add;
        __syncthreads();
    }
    if (t < NB) bsum[t] = sh[t] - v;
}

// also computes dis and xd = x*dis (padded float4)
__global__ void scan_add_kernel(int* offs, const int* __restrict__ bsum,
                                int* cur, const int* __restrict__ cnt,
                                const float* __restrict__ x,
                                float* dis, float* xd, int N, int E) {
    int i = blockIdx.x * blockDim.x + threadIdx.x;
    if (i < N) {
        int o = offs[i] + bsum[i >> 10];
        offs[i] = o;
        cur[i] = o;
        float d = rsqrtf((float)cnt[i] + 1.0f);  // +1 self loop
        dis[i] = d;
        float4 v;
        v.x = x[i * 3 + 0] * d;
        v.y = x[i * 3 + 1] * d;
        v.z = x[i * 3 + 2] * d;
        v.w = 0.f;
        *(float4*)(xd + i * 4) = v;
    }
    if (i == 0) offs[N] = E;
}

__global__ void fill_kernel(const int* __restrict__ src, const int* __restrict__ dst,
                            int* cur, int* adj, int E) {
    int i = blockIdx.x * blockDim.x + threadIdx.x;
    if (i < E) {
        int slot = atomicAdd(&cur[dst[i]], 1);
        adj[slot] = src[i];
    }
}

// ---------------------------------------------------------------------------
// prep: W2 (128x128) / W3 (128x64) -> transposed n-major [n][k], bf16 hi/lo
// ---------------------------------------------------------------------------
__global__ void prep_b_kernel(const float* __restrict__ W2, const float* __restrict__ W3,
                              __nv_bfloat16* bh2, __nv_bfloat16* bl2,
                              __nv_bfloat16* bh3, __nv_bfloat16* bl3) {
    int i = blockIdx.x * blockDim.x + threadIdx.x;
    if (i < 128 * 128) {
        int n = i >> 7, k = i & 127;
        float w = W2[k * 128 + n];
        __nv_bfloat16 hi = __float2bfloat16_rn(w);
        __nv_bfloat16 lo = __float2bfloat16_rn(w - __bfloat162float(hi));
        bh2[n * 128 + k] = hi;
        bl2[n * 128 + k] = lo;
    } else if (i < 128 * 128 + 64 * 128) {
        int j = i - 128 * 128;
        int n = j >> 7, k = j & 127;
        float w = W3[k * 64 + n];
        __nv_bfloat16 hi = __float2bfloat16_rn(w);
        __nv_bfloat16 lo = __float2bfloat16_rn(w - __bfloat162float(hi));
        bh3[n * 128 + k] = hi;
        bl3[n * 128 + k] = lo;
    }
}

// ---------------------------------------------------------------------------
// layer-1 aggregation in 3-dim space: z[d] = xd[d] + sum_{s in adj(d)} xd[s]
// One thread per node, unroll 4.
// ---------------------------------------------------------------------------
__global__ __launch_bounds__(256) void agg3_kernel(
    const int* __restrict__ offs, const int* __restrict__ adj,
    const float* __restrict__ xd, float* __restrict__ z, int N) {
    int i = blockIdx.x * blockDim.x + threadIdx.x;
    if (i >= N) return;
    int beg = offs[i];
    int end = offs[i + 1];
    const float4* xv = (const float4*)xd;
    float4 s = __ldg(&xv[i]);  // self loop
    float sx = s.x, sy = s.y, sz = s.z;
    float ux = 0.f, uy = 0.f, uz = 0.f;
    int e = beg;
    for (; e + 4 <= end; e += 4) {
        int a0 = __ldg(&adj[e]);
        int a1 = __ldg(&adj[e + 1]);
        int a2 = __ldg(&adj[e + 2]);
        int a3 = __ldg(&adj[e + 3]);
        float4 v0 = __ldg(&xv[a0]);
        float4 v1 = __ldg(&xv[a1]);
        float4 v2 = __ldg(&xv[a2]);
        float4 v3 = __ldg(&xv[a3]);
        sx += v0.x + v2.x; sy += v0.y + v2.y; sz += v0.z + v2.z;
        ux += v1.x + v3.x; uy += v1.y + v3.y; uz += v1.z + v3.z;
    }
    for (; e < end; e++) {
        int a = __ldg(&adj[e]);
        float4 v = __ldg(&xv[a]);
        sx += v.x; sy += v.y; sz += v.z;
    }
    float4 o = make_float4(sx + ux, sy + uy, sz + uz, 0.f);
    *(float4*)(z + i * 4) = o;
}

// ---------------------------------------------------------------------------
// layer-1 transform: h[n] = relu(dis[n] * (z[n] @ W1) + b1), K=3, F=128
// ---------------------------------------------------------------------------
__global__ __launch_bounds__(256) void l1t_kernel(
    const float* __restrict__ z, const float* __restrict__ W1,
    const float* __restrict__ dis, const float* __restrict__ b1,
    float* __restrict__ h, int N) {
    __shared__ float ws[3 * 128];
    __shared__ float bs[128];
    for (int i = threadIdx.x; i < 384; i += blockDim.x) ws[i] = W1[i];
    for (int i = threadIdx.x; i < 128; i += blockDim.x) bs[i] = b1[i];
    __syncthreads();
    int idx = blockIdx.x * blockDim.x + threadIdx.x;
    int n = idx >> 5;
    int l = idx & 31;
    if (n >= N) return;
    float4 zv = *(const float4*)(z + n * 4);
    float d = dis[n];
    int f = l * 4;
    float4 o;
    o.x = fmaxf(fmaf(zv.x * ws[f + 0] + zv.y * ws[128 + f + 0] + zv.z * ws[256 + f + 0], d, bs[f + 0]), 0.f);
    o.y = fmaxf(fmaf(zv.x * ws[f + 1] + zv.y * ws[128 + f + 1] + zv.z * ws[256 + f + 1], d, bs[f + 1]), 0.f);
    o.z = fmaxf(fmaf(zv.x * ws[f + 2] + zv.y * ws[128 + f + 2] + zv.z * ws[256 + f + 2], d, bs[f + 2]), 0.f);
    o.w = fmaxf(fmaf(zv.x * ws[f + 3] + zv.y * ws[128 + f + 3] + zv.z * ws[256 + f + 3], d, bs[f + 3]), 0.f);
    *(float4*)(h + (size_t)n * 128 + f) = o;
}

// ---------------------------------------------------------------------------
// bf16x3 tensor-core GEMM via mma.sync.m16n8k16 (legacy HMMA, sm_103-safe):
//   out[n] = (A[n] @ W) * dis[n],  D = Ahi*Bhi + Alo*Bhi + Ahi*Blo, fp32 accum.
// Block = 256 thr (8 warps), tile = 128 rows x F. K staged in 2 chunks of 64.
// ---------------------------------------------------------------------------
#define LDH 72  // halfs per smem row (64 + 8 pad)

template <int F>
__global__ __launch_bounds__(256) void gemm_mma_kernel(
    const float* __restrict__ A, const __nv_bfloat16* __restrict__ Bhg,
    const __nv_bfloat16* __restrict__ Blg, const float* __restrict__ dis,
    float* __restrict__ out, int N) {
    extern __shared__ __align__(16) __nv_bfloat16 smh[];
    __nv_bfloat16* Ah = smh;             // 128 x LDH
    __nv_bfloat16* Al = Ah + 128 * LDH;  // 128 x LDH
    __nv_bfloat16* Bh = Al + 128 * LDH;  // F x LDH
    __nv_bfloat16* Bl = Bh + F * LDH;    // F x LDH

    const int tid = threadIdx.x;
    const int warp = tid >> 5;
    const int lane = tid & 31;
    const int g = lane >> 2;   // 0..7
    const int tg = lane & 3;   // 0..3
    const int n0 = blockIdx.x * 128;

    constexpr int NT = F / 8;
    float acc[NT][4];
#pragma unroll
    for (int i = 0; i < NT; i++) {
        acc[i][0] = acc[i][1] = acc[i][2] = acc[i][3] = 0.f;
    }

    for (int kc = 0; kc < 128; kc += 64) {
        __syncthreads();  // protect smem from previous chunk's readers
        // stage A chunk [128 x 64] with bf16 hi/lo split
        for (int i = tid; i < 128 * 16; i += 256) {
            int r = i >> 4, c4 = i & 15;
            float4 v = make_float4(0.f, 0.f, 0.f, 0.f);
            int n = n0 + r;
            if (n < N) v = *(const float4*)(A + (size_t)n * 128 + kc + c4 * 4);
            __nv_bfloat16 h0 = __float2bfloat16_rn(v.x);
            __nv_bfloat16 h1 = __float2bfloat16_rn(v.y);
            __nv_bfloat16 h2 = __float2bfloat16_rn(v.z);
            __nv_bfloat16 h3 = __float2bfloat16_rn(v.w);
            __nv_bfloat162 hp0 = {h0, h1}, hp1 = {h2, h3};
            __nv_bfloat162 lp0 = {__float2bfloat16_rn(v.x - __bfloat162float(h0)),
                                  __float2bfloat16_rn(v.y - __bfloat162float(h1))};
            __nv_bfloat162 lp1 = {__float2bfloat16_rn(v.z - __bfloat162float(h2)),
                                  __float2bfloat16_rn(v.w - __bfloat162float(h3))};
            uint2 hu, lu;
            hu.x = *(uint32_t*)&hp0; hu.y = *(uint32_t*)&hp1;
            lu.x = *(uint32_t*)&lp0; lu.y = *(uint32_t*)&lp1;
            *(uint2*)(Ah + r * LDH + c4 * 4) = hu;
            *(uint2*)(Al + r * LDH + c4 * 4) = lu;
        }
        // stage B chunk [F x 64] (already bf16 hi/lo in global, n-major)
        for (int i = tid; i < F * 8; i += 256) {
            int r = i >> 3, c8 = i & 7;
            *(uint4*)(Bh + r * LDH + c8 * 8) = *(const uint4*)(Bhg + r * 128 + kc + c8 * 8);
            *(uint4*)(Bl + r * LDH + c8 * 8) = *(const uint4*)(Blg + r * 128 + kc + c8 * 8);
        }
        __syncthreads();

        const __nv_bfloat16* ar0 = Ah + (warp * 16 + g) * LDH + 2 * tg;
        const __nv_bfloat16* al0 = Al + (warp * 16 + g) * LDH + 2 * tg;
#pragma unroll
        for (int ks = 0; ks < 4; ks++) {
            const int ko = ks * 16;
            uint32_t ah0 = *(const uint32_t*)(ar0 + ko);
            uint32_t ah1 = *(const uint32_t*)(ar0 + 8 * LDH + ko);
            uint32_t ah2 = *(const uint32_t*)(ar0 + ko + 8);
            uint32_t ah3 = *(const uint32_t*)(ar0 + 8 * LDH + ko + 8);
            uint32_t aw0 = *(const uint32_t*)(al0 + ko);
            uint32_t aw1 = *(const uint32_t*)(al0 + 8 * LDH + ko);
            uint32_t aw2 = *(const uint32_t*)(al0 + ko + 8);
            uint32_t aw3 = *(const uint32_t*)(al0 + 8 * LDH + ko + 8);
#pragma unroll
            for (int nt = 0; nt < NT; nt++) {
                const __nv_bfloat16* bhr = Bh + (nt * 8 + g) * LDH + 2 * tg + ko;
                const __nv_bfloat16* blr = Bl + (nt * 8 + g) * LDH + 2 * tg + ko;
                uint32_t bh0 = *(const uint32_t*)bhr;
                uint32_t bh1 = *(const uint32_t*)(bhr + 8);
                uint32_t bl0 = *(const uint32_t*)blr;
                uint32_t bl1 = *(const uint32_t*)(blr + 8);
                asm volatile(
                    "mma.sync.aligned.m16n8k16.row.col.f32.bf16.bf16.f32 "
                    "{%0,%1,%2,%3}, {%4,%5,%6,%7}, {%8,%9}, {%0,%1,%2,%3};"
                    : "+f"(acc[nt][0]), "+f"(acc[nt][1]), "+f"(acc[nt][2]), "+f"(acc[nt][3])
                    : "r"(ah0), "r"(ah1), "r"(ah2), "r"(ah3), "r"(bh0), "r"(bh1));
                asm volatile(
                    "mma.sync.aligned.m16n8k16.row.col.f32.bf16.bf16.f32 "
                    "{%0,%1,%2,%3}, {%4,%5,%6,%7}, {%8,%9}, {%0,%1,%2,%3};"
                    : "+f"(acc[nt][0]), "+f"(acc[nt][1]), "+f"(acc[nt][2]), "+f"(acc[nt][3])
                    : "r"(aw0), "r"(aw1), "r"(aw2), "r"(aw3), "r"(bh0), "r"(bh1));
                asm volatile(
                    "mma.sync.aligned.m16n8k16.row.col.f32.bf16.bf16.f32 "
                    "{%0,%1,%2,%3}, {%4,%5,%6,%7}, {%8,%9}, {%0,%1,%2,%3};"
                    : "+f"(acc[nt][0]), "+f"(acc[nt][1]), "+f"(acc[nt][2]), "+f"(acc[nt][3])
                    : "r"(ah0), "r"(ah1), "r"(ah2), "r"(ah3), "r"(bl0), "r"(bl1));
            }
        }
    }

    // epilogue: c0,c1 = row g cols 2tg,2tg+1; c2,c3 = row g+8.
    int m0 = n0 + warp * 16 + g;
    int m1 = m0 + 8;
    float d0 = (m0 < N) ? dis[m0] : 0.f;
    float d1 = (m1 < N) ? dis[m1] : 0.f;
#pragma unroll
    for (int nt = 0; nt < NT; nt++) {
        if (m0 < N) {
            float2 o = make_float2(acc[nt][0] * d0, acc[nt][1] * d0);
            *(float2*)(out + (size_t)m0 * F + nt * 8 + tg * 2) = o;
        }
        if (m1 < N) {
            float2 o = make_float2(acc[nt][2] * d1, acc[nt][3] * d1);
            *(float2*)(out + (size_t)m1 * F + nt * 8 + tg * 2) = o;
        }
    }
}

// ---------------------------------------------------------------------------
// CSR gather + epilogue: h[d] = relu(dis[d]*(sum_{s in adj(d)} t[s] + t[d]) + b)
// One warp per dst node; fp32; unroll 4 for MLP.
// ---------------------------------------------------------------------------
template <int F>
__global__ __launch_bounds__(256) void gather_kernel(
    const int* __restrict__ offs, const int* __restrict__ adj,
    const float* __restrict__ t, const float* __restrict__ dis,
    const float* __restrict__ b, float* __restrict__ h, int N) {
    int node = (blockIdx.x * 256 + threadIdx.x) >> 5;
    int lane = threadIdx.x & 31;
    if (node >= N) return;
    int beg = offs[node];
    int end = offs[node + 1];
    float d = dis[node];
    if constexpr (F == 128) {
        const float4* tv = (const float4*)t;
        float4 s0 = __ldg(&tv[(size_t)node * 32 + lane]);  // self loop
        float4 s1 = make_float4(0.f, 0.f, 0.f, 0.f);
        int e = beg;
        for (; e + 4 <= end; e += 4) {
            int a0 = __ldg(&adj[e]);
            int a1 = __ldg(&adj[e + 1]);
            int a2 = __ldg(&adj[e + 2]);
            int a3 = __ldg(&adj[e + 3]);
            float4 v0 = __ldg(&tv[(size_t)a0 * 32 + lane]);
            float4 v1 = __ldg(&tv[(size_t)a1 * 32 + lane]);
            float4 v2 = __ldg(&tv[(size_t)a2 * 32 + lane]);
            float4 v3 = __ldg(&tv[(size_t)a3 * 32 + lane]);
            s0.x += v0.x + v2.x; s0.y += v0.y + v2.y;
            s0.z += v0.z + v2.z; s0.w += v0.w + v2.w;
            s1.x += v1.x + v3.x; s1.y += v1.y + v3.y;
            s1.z += v1.z + v3.z; s1.w += v1.w + v3.w;
        }
        for (; e < end; e++) {
            int a = __ldg(&adj[e]);
            float4 v = __ldg(&tv[(size_t)a * 32 + lane]);
            s0.x += v.x; s0.y += v.y; s0.z += v.z; s0.w += v.w;
        }
        float4 bv = __ldg(&((const float4*)b)[lane]);
        float4 o;
        o.x = fmaxf(fmaf(s0.x + s1.x, d, bv.x), 0.f);
        o.y = fmaxf(fmaf(s0.y + s1.y, d, bv.y), 0.f);
        o.z = fmaxf(fmaf(s0.z + s1.z, d, bv.z), 0.f);
        o.w = fmaxf(fmaf(s0.w + s1.w, d, bv.w), 0.f);
        ((float4*)h)[(size_t)node * 32 + lane] = o;
    } else {
        const float2* tv = (const float2*)t;
        float2 s0 = __ldg(&tv[(size_t)node * 32 + lane]);
        float2 s1 = make_float2(0.f, 0.f);
        int e = beg;
        for (; e + 4 <= end; e += 4) {
            int a0 = __ldg(&adj[e]);
            int a1 = __ldg(&adj[e + 1]);
            int a2 = __ldg(&adj[e + 2]);
            int a3 = __ldg(&adj[e + 3]);
            float2 v0 = __ldg(&tv[(size_t)a0 * 32 + lane]);
            float2 v1 = __ldg(&tv[(size_t)a1 * 32 + lane]);
            float2 v2 = __ldg(&tv[(size_t)a2 * 32 + lane]);
            float2 v3 = __ldg(&tv[(size_t)a3 * 32 + lane]);
            s0.x += v0.x + v2.x; s0.y += v0.y + v2.y;
            s1.x += v1.x + v3.x; s1.y += v1.y + v3.y;
        }
        for (; e < end; e++) {
            int a = __ldg(&adj[e]);
            float2 v = __ldg(&tv[(size_t)a * 32 + lane]);
            s0.x += v.x; s0.y += v.y;
        }
        float2 bv = __ldg(&((const float2*)b)[lane]);
        float2 o;
        o.x = fmaxf(fmaf(s0.x + s1.x, d, bv.x), 0.f);
        o.y = fmaxf(fmaf(s0.y + s1.y, d, bv.y), 0.f);
        ((float2*)h)[(size_t)node * 32 + lane] = o;
    }
}

// ---------------------------------------------------------------------------
// pooling: batch sorted -> segmented reduction, atomic flush at boundaries
// ---------------------------------------------------------------------------
__global__ __launch_bounds__(64) void pool_kernel(
    const float* __restrict__ h, const int* __restrict__ batch,
    float* __restrict__ sums, float* __restrict__ cnt, int N) {
    int start = blockIdx.x * 256;
    int end = min(start + 256, N);
    int f = threadIdx.x;
    int g = batch[start];
    float s = 0.f, c = 0.f;
    for (int n = start; n < end; n++) {
        int bn = batch[n];
        if (bn != g) {
            atomicAdd(&sums[g * 64 + f], s);
            if (f == 0) atomicAdd(&cnt[g], c);
            s = 0.f; c = 0.f; g = bn;
        }
        s += h[(size_t)n * 64 + f];
        c += 1.f;
    }
    atomicAdd(&sums[g * 64 + f], s);
    if (f == 0) atomicAdd(&cnt[g], c);
}

__global__ void final_kernel(const float* __restrict__ sums, const float* __restrict__ cnt,
                             const float* __restrict__ Wl, const float* __restrict__ bl,
                             float* __restrict__ out) {
    int g = blockIdx.x * blockDim.x + threadIdx.x;
    if (g >= NG_GRAPHS) return;
    float c = fmaxf(cnt[g], 1.0f);
    float acc = 0.f;
#pragma unroll
    for (int f = 0; f < 64; f++) acc = fmaf(sums[g * 64 + f], Wl[f], acc);
    out[g] = acc / c + bl[0];
}

// ---------------------------------------------------------------------------
extern "C" void kernel_launch(void* const* d_in, const int* in_sizes, int n_in,
                              void* d_out, int out_size) {
    const float* x     = (const float*)d_in[0];
    const int*   ei    = (const int*)d_in[1];    // int32
    const int*   batch = (const int*)d_in[2];    // int32
    const float* W1 = (const float*)d_in[3];
    const float* b1 = (const float*)d_in[4];
    const float* W2 = (const float*)d_in[5];
    const float* b2 = (const float*)d_in[6];
    const float* W3 = (const float*)d_in[7];
    const float* b3 = (const float*)d_in[8];
    const float* Wl = (const float*)d_in[9];
    const float* bl = (const float*)d_in[10];
    float* out = (float*)d_out;

    const int N = in_sizes[0] / 3;
    const int E = in_sizes[1] / 2;
    const int* srcp = ei;
    const int* dstp = ei + E;

    float *t, *h, *xd, *z, *dis, *sums, *gcnt;
    __nv_bfloat16 *bh2, *bl2, *bh3, *bl3;
    int *cnt, *offs, *cur, *adj, *bsum;
    cudaGetSymbolAddress((void**)&t, g_t);
    cudaGetSymbolAddress((void**)&h, g_h);
    cudaGetSymbolAddress((void**)&xd, g_xd);
    cudaGetSymbolAddress((void**)&z, g_z);
    cudaGetSymbolAddress((void**)&bh2, g_bh2);
    cudaGetSymbolAddress((void**)&bl2, g_bl2);
    cudaGetSymbolAddress((void**)&bh3, g_bh3);
    cudaGetSymbolAddress((void**)&bl3, g_bl3);
    cudaGetSymbolAddress((void**)&dis, g_dis);
    cudaGetSymbolAddress((void**)&cnt, g_cnt);
    cudaGetSymbolAddress((void**)&offs, g_offs);
    cudaGetSymbolAddress((void**)&cur, g_cur);
    cudaGetSymbolAddress((void**)&adj, g_adj);
    cudaGetSymbolAddress((void**)&bsum, g_bsum);
    cudaGetSymbolAddress((void**)&sums, g_sums);
    cudaGetSymbolAddress((void**)&gcnt, g_gcnt);

    // smem: (128 A rows hi+lo + F B rows hi+lo) x LDH halfs
    const int SMEM128 = (2 * 128 + 2 * 128) * LDH * 2;  // 73,728 B
    const int SMEM64  = (2 * 128 + 2 * 64) * LDH * 2;   // 55,296 B
    cudaFuncSetAttribute(gemm_mma_kernel<128>,
                         cudaFuncAttributeMaxDynamicSharedMemorySize, SMEM128);
    cudaFuncSetAttribute(gemm_mma_kernel<64>,
                         cudaFuncAttributeMaxDynamicSharedMemorySize, SMEM64);

    const int nB = (N + 255) / 256;
    const int eB = (E + 255) / 256;
    const int NB_SCAN = (N + SCAN_B - 1) / SCAN_B;
    const int wB = (N * 32 + 255) / 256;      // warp-per-node grids
    const int gB = (N + 127) / 128;           // gemm grids

    // --- CSR build (once, reused for all 3 layers) ---
    cudaMemsetAsync(cnt, 0, (size_t)N * sizeof(int), 0);
    count_kernel<<<eB, 256>>>(dstp, cnt, E);
    scan_block_kernel<<<NB_SCAN, SCAN_B>>>(cnt, offs, bsum, N);
    scan_top_kernel<<<1, 128>>>(bsum, NB_SCAN);
    scan_add_kernel<<<nB, 256>>>(offs, bsum, cur, cnt, x, dis, xd, N, E);
    fill_kernel<<<eB, 256>>>(srcp, dstp, cur, adj, E);
    prep_b_kernel<<<(128 * 128 + 64 * 128 + 255) / 256, 256>>>(W2, W3, bh2, bl2, bh3, bl3);

    // --- layer 1 (3 -> 128): aggregate in 3-dim, then transform ---
    agg3_kernel<<<nB, 256>>>(offs, adj, xd, z, N);
    l1t_kernel<<<wB, 256>>>(z, W1, dis, b1, h, N);

    // --- layer 2 (128 -> 128) ---
    gemm_mma_kernel<128><<<gB, 256, SMEM128>>>(h, bh2, bl2, dis, t, N);
    gather_kernel<128><<<wB, 256>>>(offs, adj, t, dis, b2, h, N);

    // --- layer 3 (128 -> 64) ---
    gemm_mma_kernel<64><<<gB, 256, SMEM64>>>(h, bh3, bl3, dis, t, N);
    gather_kernel<64><<<wB, 256>>>(offs, adj, t, dis, b3, h, N);

    // --- pooling + final linear ---
    cudaMemsetAsync(sums, 0, NG_GRAPHS * 64 * sizeof(float), 0);
    cudaMemsetAsync(gcnt, 0, NG_GRAPHS * sizeof(float), 0);
    pool_kernel<<<(N + 255) / 256, 64>>>(h, batch, sums, gcnt, N);
    final_kernel<<<2, 256>>>(sums, gcnt, Wl, bl, out);
}

// round 9
// speedup vs baseline: 1.8582x; 1.1537x over previous
#include <cuda_runtime.h>
#include <cuda_bf16.h>
#include <cstdint>

#define MAXN 100000
#define MAXE 600000
#define NG_GRAPHS 512
#define SCAN_B 1024

// Scratch (static device globals; allocation-free).
// NOTE: g_cnt relies on (a) CUDA zero-init of device globals for the first
// call, (b) scan_add_kernel re-zeroing it at the end of every call.
__device__ __align__(16) float g_t[MAXN * 128];
__device__ __align__(16) float g_h[MAXN * 128];
__device__ __align__(16) float g_xd[MAXN * 4];   // x * dis, padded float4
__device__ __align__(16) __nv_bfloat16 g_bh2[128 * 128];  // W2^T hi (n-major [n][k])
__device__ __align__(16) __nv_bfloat16 g_bl2[128 * 128];  // W2^T lo
__device__ __align__(16) __nv_bfloat16 g_bh3[64 * 128];   // W3^T hi
__device__ __align__(16) __nv_bfloat16 g_bl3[64 * 128];   // W3^T lo
__device__ __align__(16) float g_dis[MAXN];
__device__ __align__(16) int   g_cnt[MAXN];
__device__ __align__(16) int   g_offs[MAXN + 1];
__device__ __align__(16) int   g_cur[MAXN];
__device__ __align__(16) int   g_adj[MAXE];
__device__ __align__(16) int   g_bsum[128];
__device__ __align__(16) float g_sums[NG_GRAPHS * 64];
__device__ __align__(16) float g_gcnt[NG_GRAPHS];

// ---------------------------------------------------------------------------
// count in-degrees; also zero pooling buffers (independent, saves launches)
// ---------------------------------------------------------------------------
__global__ void count_kernel(const int* __restrict__ dst, int* cnt,
                             float* sums, float* gcnt, int E) {
    int i = blockIdx.x * blockDim.x + threadIdx.x;
    if (i < E) atomicAdd(&cnt[dst[i]], 1);
    if (i < NG_GRAPHS * 64) sums[i] = 0.f;
    if (i < NG_GRAPHS) gcnt[i] = 0.f;
}

__global__ __launch_bounds__(SCAN_B) void scan_block_kernel(
    const int* __restrict__ cnt, int* offs, int* bsum, int N) {
    __shared__ int sh[SCAN_B];
    int t = threadIdx.x;
    int i = blockIdx.x * SCAN_B + t;
    int v = (i < N) ? cnt[i] : 0;
    sh[t] = v;
    __syncthreads();
#pragma unroll
    for (int off = 1; off < SCAN_B; off <<= 1) {
        int add = (t >= off) ? sh[t - off] : 0;
        __syncthreads();
        sh[t] += add;
        __syncthreads();
    }
    if (i < N) offs[i] = sh[t] - v;  // exclusive within tile
    if (t == SCAN_B - 1) bsum[blockIdx.x] = sh[t];  // tile total (raw)
}

// apply top-level scan (computed in-block over <=98 tile totals), finalize
// offs/cur, compute dis and xd = x*dis, and self-clear cnt for the next call.
__global__ __launch_bounds__(256) void scan_add_kernel(
    int* offs, const int* __restrict__ bsum, int* cur, int* cnt,
    const float* __restrict__ x, float* dis, float* xd, int N, int E) {
    __shared__ int base_sh;
    int tile = blockIdx.x >> 2;  // 256-thread block lies inside one 1024 tile
    if (threadIdx.x < 32) {
        int s = 0;
        for (int j = threadIdx.x; j < tile; j += 32) s += bsum[j];
#pragma unroll
        for (int o = 16; o; o >>= 1) s += __shfl_down_sync(0xFFFFFFFFu, s, o);
        if (threadIdx.x == 0) base_sh = s;
    }
    __syncthreads();
    int i = blockIdx.x * 256 + threadIdx.x;
    if (i < N) {
        int o = offs[i] + base_sh;
        offs[i] = o;
        cur[i] = o;
        float d = rsqrtf((float)cnt[i] + 1.0f);  // +1 self loop
        cnt[i] = 0;                              // reset for next call
        dis[i] = d;
        float4 v;
        v.x = x[i * 3 + 0] * d;
        v.y = x[i * 3 + 1] * d;
        v.z = x[i * 3 + 2] * d;
        v.w = 0.f;
        *(float4*)(xd + i * 4) = v;
    }
    if (i == 0) offs[N] = E;
}

// ---------------------------------------------------------------------------
// fused: CSR fill + W2/W3 transpose/split prep (independent work, one launch)
// ---------------------------------------------------------------------------
__global__ void fill_prep_kernel(const int* __restrict__ src, const int* __restrict__ dst,
                                 int* cur, int* adj, int E,
                                 const float* __restrict__ W2, const float* __restrict__ W3,
                                 __nv_bfloat16* bh2, __nv_bfloat16* bl2,
                                 __nv_bfloat16* bh3, __nv_bfloat16* bl3) {
    int i = blockIdx.x * blockDim.x + threadIdx.x;
    if (i < E) {
        int slot = atomicAdd(&cur[dst[i]], 1);
        adj[slot] = src[i];
        return;
    }
    int k = i - E;
    if (k < 128 * 128) {
        int n = k >> 7, kk = k & 127;
        float w = W2[kk * 128 + n];
        __nv_bfloat16 hi = __float2bfloat16_rn(w);
        __nv_bfloat16 lo = __float2bfloat16_rn(w - __bfloat162float(hi));
        bh2[n * 128 + kk] = hi;
        bl2[n * 128 + kk] = lo;
    } else if (k < 128 * 128 + 64 * 128) {
        int j = k - 128 * 128;
        int n = j >> 7, kk = j & 127;
        float w = W3[kk * 64 + n];
        __nv_bfloat16 hi = __float2bfloat16_rn(w);
        __nv_bfloat16 lo = __float2bfloat16_rn(w - __bfloat162float(hi));
        bh3[n * 128 + kk] = hi;
        bl3[n * 128 + kk] = lo;
    }
}

// ---------------------------------------------------------------------------
// fused layer 1: warp per node.
//   z = xd[n] + sum_{s in adj(n)} xd[s]   (lane-strided + shfl reduce)
//   h[n] = relu(dis[n] * (z @ W1) + b1)   (lane -> 4 features)
// ---------------------------------------------------------------------------
__global__ __launch_bounds__(256) void l1_fused_kernel(
    const int* __restrict__ offs, const int* __restrict__ adj,
    const float* __restrict__ xd, const float* __restrict__ W1,
    const float* __restrict__ dis, const float* __restrict__ b1,
    float* __restrict__ h, int N) {
    __shared__ float ws[3 * 128];
    __shared__ float bs[128];
    for (int i = threadIdx.x; i < 384; i += blockDim.x) ws[i] = W1[i];
    for (int i = threadIdx.x; i < 128; i += blockDim.x) bs[i] = b1[i];
    __syncthreads();
    int node = (blockIdx.x * 256 + threadIdx.x) >> 5;
    int lane = threadIdx.x & 31;
    if (node >= N) return;
    int beg = offs[node];
    int end = offs[node + 1];
    const float4* xv = (const float4*)xd;
    float sx = 0.f, sy = 0.f, sz = 0.f;
    for (int e = beg + lane; e < end; e += 32) {
        int a = __ldg(&adj[e]);
        float4 v = __ldg(&xv[a]);
        sx += v.x; sy += v.y; sz += v.z;
    }
#pragma unroll
    for (int o = 16; o; o >>= 1) {
        sx += __shfl_xor_sync(0xFFFFFFFFu, sx, o);
        sy += __shfl_xor_sync(0xFFFFFFFFu, sy, o);
        sz += __shfl_xor_sync(0xFFFFFFFFu, sz, o);
    }
    float4 self = __ldg(&xv[node]);
    sx += self.x; sy += self.y; sz += self.z;
    float d = dis[node];
    int f = lane * 4;
    float4 o;
    o.x = fmaxf(fmaf(sx * ws[f + 0] + sy * ws[128 + f + 0] + sz * ws[256 + f + 0], d, bs[f + 0]), 0.f);
    o.y = fmaxf(fmaf(sx * ws[f + 1] + sy * ws[128 + f + 1] + sz * ws[256 + f + 1], d, bs[f + 1]), 0.f);
    o.z = fmaxf(fmaf(sx * ws[f + 2] + sy * ws[128 + f + 2] + sz * ws[256 + f + 2], d, bs[f + 2]), 0.f);
    o.w = fmaxf(fmaf(sx * ws[f + 3] + sy * ws[128 + f + 3] + sz * ws[256 + f + 3], d, bs[f + 3]), 0.f);
    *(float4*)(h + (size_t)node * 128 + f) = o;
}

// ---------------------------------------------------------------------------
// bf16x3 tensor-core GEMM via mma.sync.m16n8k16 (legacy HMMA, sm_103-safe):
//   out[n] = (A[n] @ W) * dis[n],  D = Ahi*Bhi + Alo*Bhi + Ahi*Blo, fp32 accum.
// Block = 256 thr (8 warps), tile = 128 rows x F. K staged in 2 chunks of 64.
// ---------------------------------------------------------------------------
#define LDH 72  // halfs per smem row (64 + 8 pad)

template <int F>
__global__ __launch_bounds__(256) void gemm_mma_kernel(
    const float* __restrict__ A, const __nv_bfloat16* __restrict__ Bhg,
    const __nv_bfloat16* __restrict__ Blg, const float* __restrict__ dis,
    float* __restrict__ out, int N) {
    extern __shared__ __align__(16) __nv_bfloat16 smh[];
    __nv_bfloat16* Ah = smh;             // 128 x LDH
    __nv_bfloat16* Al = Ah + 128 * LDH;  // 128 x LDH
    __nv_bfloat16* Bh = Al + 128 * LDH;  // F x LDH
    __nv_bfloat16* Bl = Bh + F * LDH;    // F x LDH

    const int tid = threadIdx.x;
    const int warp = tid >> 5;
    const int lane = tid & 31;
    const int g = lane >> 2;   // 0..7
    const int tg = lane & 3;   // 0..3
    const int n0 = blockIdx.x * 128;

    constexpr int NT = F / 8;
    float acc[NT][4];
#pragma unroll
    for (int i = 0; i < NT; i++) {
        acc[i][0] = acc[i][1] = acc[i][2] = acc[i][3] = 0.f;
    }

    for (int kc = 0; kc < 128; kc += 64) {
        __syncthreads();  // protect smem from previous chunk's readers
        // stage A chunk [128 x 64] with bf16 hi/lo split
        for (int i = tid; i < 128 * 16; i += 256) {
            int r = i >> 4, c4 = i & 15;
            float4 v = make_float4(0.f, 0.f, 0.f, 0.f);
            int n = n0 + r;
            if (n < N) v = *(const float4*)(A + (size_t)n * 128 + kc + c4 * 4);
            __nv_bfloat16 h0 = __float2bfloat16_rn(v.x);
            __nv_bfloat16 h1 = __float2bfloat16_rn(v.y);
            __nv_bfloat16 h2 = __float2bfloat16_rn(v.z);
            __nv_bfloat16 h3 = __float2bfloat16_rn(v.w);
            __nv_bfloat162 hp0 = {h0, h1}, hp1 = {h2, h3};
            __nv_bfloat162 lp0 = {__float2bfloat16_rn(v.x - __bfloat162float(h0)),
                                  __float2bfloat16_rn(v.y - __bfloat162float(h1))};
            __nv_bfloat162 lp1 = {__float2bfloat16_rn(v.z - __bfloat162float(h2)),
                                  __float2bfloat16_rn(v.w - __bfloat162float(h3))};
            uint2 hu, lu;
            hu.x = *(uint32_t*)&hp0; hu.y = *(uint32_t*)&hp1;
            lu.x = *(uint32_t*)&lp0; lu.y = *(uint32_t*)&lp1;
            *(uint2*)(Ah + r * LDH + c4 * 4) = hu;
            *(uint2*)(Al + r * LDH + c4 * 4) = lu;
        }
        // stage B chunk [F x 64] (already bf16 hi/lo in global, n-major)
        for (int i = tid; i < F * 8; i += 256) {
            int r = i >> 3, c8 = i & 7;
            *(uint4*)(Bh + r * LDH + c8 * 8) = *(const uint4*)(Bhg + r * 128 + kc + c8 * 8);
            *(uint4*)(Bl + r * LDH + c8 * 8) = *(const uint4*)(Blg + r * 128 + kc + c8 * 8);
        }
        __syncthreads();

        const __nv_bfloat16* ar0 = Ah + (warp * 16 + g) * LDH + 2 * tg;
        const __nv_bfloat16* al0 = Al + (warp * 16 + g) * LDH + 2 * tg;
#pragma unroll
        for (int ks = 0; ks < 4; ks++) {
            const int ko = ks * 16;
            uint32_t ah0 = *(const uint32_t*)(ar0 + ko);
            uint32_t ah1 = *(const uint32_t*)(ar0 + 8 * LDH + ko);
            uint32_t ah2 = *(const uint32_t*)(ar0 + ko + 8);
            uint32_t ah3 = *(const uint32_t*)(ar0 + 8 * LDH + ko + 8);
            uint32_t aw0 = *(const uint32_t*)(al0 + ko);
            uint32_t aw1 = *(const uint32_t*)(al0 + 8 * LDH + ko);
            uint32_t aw2 = *(const uint32_t*)(al0 + ko + 8);
            uint32_t aw3 = *(const uint32_t*)(al0 + 8 * LDH + ko + 8);
#pragma unroll
            for (int nt = 0; nt < NT; nt++) {
                const __nv_bfloat16* bhr = Bh + (nt * 8 + g) * LDH + 2 * tg + ko;
                const __nv_bfloat16* blr = Bl + (nt * 8 + g) * LDH + 2 * tg + ko;
                uint32_t bh0 = *(const uint32_t*)bhr;
                uint32_t bh1 = *(const uint32_t*)(bhr + 8);
                uint32_t bl0 = *(const uint32_t*)blr;
                uint32_t bl1 = *(const uint32_t*)(blr + 8);
                asm volatile(
                    "mma.sync.aligned.m16n8k16.row.col.f32.bf16.bf16.f32 "
                    "{%0,%1,%2,%3}, {%4,%5,%6,%7}, {%8,%9}, {%0,%1,%2,%3};"
                    : "+f"(acc[nt][0]), "+f"(acc[nt][1]), "+f"(acc[nt][2]), "+f"(acc[nt][3])
                    : "r"(ah0), "r"(ah1), "r"(ah2), "r"(ah3), "r"(bh0), "r"(bh1));
                asm volatile(
                    "mma.sync.aligned.m16n8k16.row.col.f32.bf16.bf16.f32 "
                    "{%0,%1,%2,%3}, {%4,%5,%6,%7}, {%8,%9}, {%0,%1,%2,%3};"
                    : "+f"(acc[nt][0]), "+f"(acc[nt][1]), "+f"(acc[nt][2]), "+f"(acc[nt][3])
                    : "r"(aw0), "r"(aw1), "r"(aw2), "r"(aw3), "r"(bh0), "r"(bh1));
                asm volatile(
                    "mma.sync.aligned.m16n8k16.row.col.f32.bf16.bf16.f32 "
                    "{%0,%1,%2,%3}, {%4,%5,%6,%7}, {%8,%9}, {%0,%1,%2,%3};"
                    : "+f"(acc[nt][0]), "+f"(acc[nt][1]), "+f"(acc[nt][2]), "+f"(acc[nt][3])
                    : "r"(ah0), "r"(ah1), "r"(ah2), "r"(ah3), "r"(bl0), "r"(bl1));
            }
        }
    }

    // epilogue: c0,c1 = row g cols 2tg,2tg+1; c2,c3 = row g+8.
    int m0 = n0 + warp * 16 + g;
    int m1 = m0 + 8;
    float d0 = (m0 < N) ? dis[m0] : 0.f;
    float d1 = (m1 < N) ? dis[m1] : 0.f;
#pragma unroll
    for (int nt = 0; nt < NT; nt++) {
        if (m0 < N) {
            float2 o = make_float2(acc[nt][0] * d0, acc[nt][1] * d0);
            *(float2*)(out + (size_t)m0 * F + nt * 8 + tg * 2) = o;
        }
        if (m1 < N) {
            float2 o = make_float2(acc[nt][2] * d1, acc[nt][3] * d1);
            *(float2*)(out + (size_t)m1 * F + nt * 8 + tg * 2) = o;
        }
    }
}

// ---------------------------------------------------------------------------
// CSR gather + epilogue: h[d] = relu(dis[d]*(sum_{s in adj(d)} t[s] + t[d]) + b)
// One warp per dst node; fp32; unroll 4 for MLP.
// ---------------------------------------------------------------------------
template <int F>
__global__ __launch_bounds__(256) void gather_kernel(
    const int* __restrict__ offs, const int* __restrict__ adj,
    const float* __restrict__ t, const float* __restrict__ dis,
    const float* __restrict__ b, float* __restrict__ h, int N) {
    int node = (blockIdx.x * 256 + threadIdx.x) >> 5;
    int lane = threadIdx.x & 31;
    if (node >= N) return;
    int beg = offs[node];
    int end = offs[node + 1];
    float d = dis[node];
    if constexpr (F == 128) {
        const float4* tv = (const float4*)t;
        float4 s0 = __ldg(&tv[(size_t)node * 32 + lane]);  // self loop
        float4 s1 = make_float4(0.f, 0.f, 0.f, 0.f);
        int e = beg;
        for (; e + 4 <= end; e += 4) {
            int a0 = __ldg(&adj[e]);
            int a1 = __ldg(&adj[e + 1]);
            int a2 = __ldg(&adj[e + 2]);
            int a3 = __ldg(&adj[e + 3]);
            float4 v0 = __ldg(&tv[(size_t)a0 * 32 + lane]);
            float4 v1 = __ldg(&tv[(size_t)a1 * 32 + lane]);
            float4 v2 = __ldg(&tv[(size_t)a2 * 32 + lane]);
            float4 v3 = __ldg(&tv[(size_t)a3 * 32 + lane]);
            s0.x += v0.x + v2.x; s0.y += v0.y + v2.y;
            s0.z += v0.z + v2.z; s0.w += v0.w + v2.w;
            s1.x += v1.x + v3.x; s1.y += v1.y + v3.y;
            s1.z += v1.z + v3.z; s1.w += v1.w + v3.w;
        }
        for (; e < end; e++) {
            int a = __ldg(&adj[e]);
            float4 v = __ldg(&tv[(size_t)a * 32 + lane]);
            s0.x += v.x; s0.y += v.y; s0.z += v.z; s0.w += v.w;
        }
        float4 bv = __ldg(&((const float4*)b)[lane]);
        float4 o;
        o.x = fmaxf(fmaf(s0.x + s1.x, d, bv.x), 0.f);
        o.y = fmaxf(fmaf(s0.y + s1.y, d, bv.y), 0.f);
        o.z = fmaxf(fmaf(s0.z + s1.z, d, bv.z), 0.f);
        o.w = fmaxf(fmaf(s0.w + s1.w, d, bv.w), 0.f);
        ((float4*)h)[(size_t)node * 32 + lane] = o;
    } else {
        const float2* tv = (const float2*)t;
        float2 s0 = __ldg(&tv[(size_t)node * 32 + lane]);
        float2 s1 = make_float2(0.f, 0.f);
        int e = beg;
        for (; e + 4 <= end; e += 4) {
            int a0 = __ldg(&adj[e]);
            int a1 = __ldg(&adj[e + 1]);
            int a2 = __ldg(&adj[e + 2]);
            int a3 = __ldg(&adj[e + 3]);
            float2 v0 = __ldg(&tv[(size_t)a0 * 32 + lane]);
            float2 v1 = __ldg(&tv[(size_t)a1 * 32 + lane]);
            float2 v2 = __ldg(&tv[(size_t)a2 * 32 + lane]);
            float2 v3 = __ldg(&tv[(size_t)a3 * 32 + lane]);
            s0.x += v0.x + v2.x; s0.y += v0.y + v2.y;
            s1.x += v1.x + v3.x; s1.y += v1.y + v3.y;
        }
        for (; e < end; e++) {
            int a = __ldg(&adj[e]);
            float2 v = __ldg(&tv[(size_t)a * 32 + lane]);
            s0.x += v.x; s0.y += v.y;
        }
        float2 bv = __ldg(&((const float2*)b)[lane]);
        float2 o;
        o.x = fmaxf(fmaf(s0.x + s1.x, d, bv.x), 0.f);
        o.y = fmaxf(fmaf(s0.y + s1.y, d, bv.y), 0.f);
        ((float2*)h)[(size_t)node * 32 + lane] = o;
    }
}

// ---------------------------------------------------------------------------
// pooling: batch sorted -> segmented reduction. Block = 256 thr = 4 groups of
// 64 features; each group reduces a 64-node segment (4x parallelism vs R8).
// ---------------------------------------------------------------------------
__global__ __launch_bounds__(256) void pool_kernel(
    const float* __restrict__ h, const int* __restrict__ batch,
    float* __restrict__ sums, float* __restrict__ cnt, int N) {
    int grp = threadIdx.x >> 6;
    int f = threadIdx.x & 63;
    int start = blockIdx.x * 256 + grp * 64;
    if (start >= N) return;
    int end = min(start + 64, N);
    int g = batch[start];
    float s = 0.f, c = 0.f;
    for (int n = start; n < end; n++) {
        int bn = batch[n];
        if (bn != g) {
            atomicAdd(&sums[g * 64 + f], s);
            if (f == 0) atomicAdd(&cnt[g], c);
            s = 0.f; c = 0.f; g = bn;
        }
        s += h[(size_t)n * 64 + f];
        c += 1.f;
    }
    atomicAdd(&sums[g * 64 + f], s);
    if (f == 0) atomicAdd(&cnt[g], c);
}

__global__ void final_kernel(const float* __restrict__ sums, const float* __restrict__ cnt,
                             const float* __restrict__ Wl, const float* __restrict__ bl,
                             float* __restrict__ out) {
    int g = blockIdx.x * blockDim.x + threadIdx.x;
    if (g >= NG_GRAPHS) return;
    float c = fmaxf(cnt[g], 1.0f);
    float acc = 0.f;
#pragma unroll
    for (int f = 0; f < 64; f++) acc = fmaf(sums[g * 64 + f], Wl[f], acc);
    out[g] = acc / c + bl[0];
}

// ---------------------------------------------------------------------------
extern "C" void kernel_launch(void* const* d_in, const int* in_sizes, int n_in,
                              void* d_out, int out_size) {
    const float* x     = (const float*)d_in[0];
    const int*   ei    = (const int*)d_in[1];    // int32
    const int*   batch = (const int*)d_in[2];    // int32
    const float* W1 = (const float*)d_in[3];
    const float* b1 = (const float*)d_in[4];
    const float* W2 = (const float*)d_in[5];
    const float* b2 = (const float*)d_in[6];
    const float* W3 = (const float*)d_in[7];
    const float* b3 = (const float*)d_in[8];
    const float* Wl = (const float*)d_in[9];
    const float* bl = (const float*)d_in[10];
    float* out = (float*)d_out;

    const int N = in_sizes[0] / 3;
    const int E = in_sizes[1] / 2;
    const int* srcp = ei;
    const int* dstp = ei + E;

    float *t, *h, *xd, *dis, *sums, *gcnt;
    __nv_bfloat16 *bh2, *bl2, *bh3, *bl3;
    int *cnt, *offs, *cur, *adj, *bsum;
    cudaGetSymbolAddress((void**)&t, g_t);
    cudaGetSymbolAddress((void**)&h, g_h);
    cudaGetSymbolAddress((void**)&xd, g_xd);
    cudaGetSymbolAddress((void**)&bh2, g_bh2);
    cudaGetSymbolAddress((void**)&bl2, g_bl2);
    cudaGetSymbolAddress((void**)&bh3, g_bh3);
    cudaGetSymbolAddress((void**)&bl3, g_bl3);
    cudaGetSymbolAddress((void**)&dis, g_dis);
    cudaGetSymbolAddress((void**)&cnt, g_cnt);
    cudaGetSymbolAddress((void**)&offs, g_offs);
    cudaGetSymbolAddress((void**)&cur, g_cur);
    cudaGetSymbolAddress((void**)&adj, g_adj);
    cudaGetSymbolAddress((void**)&bsum, g_bsum);
    cudaGetSymbolAddress((void**)&sums, g_sums);
    cudaGetSymbolAddress((void**)&gcnt, g_gcnt);

    // smem: (128 A rows hi+lo + F B rows hi+lo) x LDH halfs
    const int SMEM128 = (2 * 128 + 2 * 128) * LDH * 2;  // 73,728 B
    const int SMEM64  = (2 * 128 + 2 * 64) * LDH * 2;   // 55,296 B
    cudaFuncSetAttribute(gemm_mma_kernel<128>,
                         cudaFuncAttributeMaxDynamicSharedMemorySize, SMEM128);
    cudaFuncSetAttribute(gemm_mma_kernel<64>,
                         cudaFuncAttributeMaxDynamicSharedMemorySize, SMEM64);

    const int nB = (N + 255) / 256;
    const int eB = (E + 255) / 256;
    const int NB_SCAN = (N + SCAN_B - 1) / SCAN_B;
    const int wB = (N * 32 + 255) / 256;      // warp-per-node grids
    const int gB = (N + 127) / 128;           // gemm grids
    const int fpB = (E + 128 * 128 + 64 * 128 + 255) / 256;

    // --- CSR build + prep (cnt is zero at entry: zero-init on call 1, ---
    // --- self-cleared by scan_add on every call)                      ---
    count_kernel<<<eB, 256>>>(dstp, cnt, sums, gcnt, E);
    scan_block_kernel<<<NB_SCAN, SCAN_B>>>(cnt, offs, bsum, N);
    scan_add_kernel<<<nB, 256>>>(offs, bsum, cur, cnt, x, dis, xd, N, E);
    fill_prep_kernel<<<fpB, 256>>>(srcp, dstp, cur, adj, E,
                                   W2, W3, bh2, bl2, bh3, bl3);

    // --- layer 1 (3 -> 128): fused aggregate + transform ---
    l1_fused_kernel<<<wB, 256>>>(offs, adj, xd, W1, dis, b1, h, N);

    // --- layer 2 (128 -> 128) ---
    gemm_mma_kernel<128><<<gB, 256, SMEM128>>>(h, bh2, bl2, dis, t, N);
    gather_kernel<128><<<wB, 256>>>(offs, adj, t, dis, b2, h, N);

    // --- layer 3 (128 -> 64) ---
    gemm_mma_kernel<64><<<gB, 256, SMEM64>>>(h, bh3, bl3, dis, t, N);
    gather_kernel<64><<<wB, 256>>>(offs, adj, t, dis, b3, h, N);

    // --- pooling + final linear ---
    pool_kernel<<<nB, 256>>>(h, batch, sums, gcnt, N);
    final_kernel<<<2, 256>>>(sums, gcnt, Wl, bl, out);
}

// round 10
// speedup vs baseline: 1.9921x; 1.0721x over previous
#include <cuda_runtime.h>
#include <cuda_bf16.h>
#include <cuda_fp16.h>
#include <cstdint>

#define MAXN 100000
#define MAXE 600000
#define NG_GRAPHS 512
#define SCAN_B 1024

// Scratch (static device globals; allocation-free).
// NOTE: g_cnt relies on (a) CUDA zero-init of device globals for the first
// call, (b) scan_add_kernel re-zeroing it at the end of every call.
__device__ __align__(16) __half g_t[MAXN * 128];   // fp16 GEMM output (gather payload)
__device__ __align__(16) float g_h[MAXN * 128];    // fp32 activations
__device__ __align__(16) float g_xd[MAXN * 4];     // x * dis, padded float4
__device__ __align__(16) __nv_bfloat16 g_bh2[128 * 128];  // W2^T hi (n-major [n][k])
__device__ __align__(16) __nv_bfloat16 g_bl2[128 * 128];  // W2^T lo
__device__ __align__(16) __nv_bfloat16 g_bh3[64 * 128];   // W3^T hi
__device__ __align__(16) __nv_bfloat16 g_bl3[64 * 128];   // W3^T lo
__device__ __align__(16) float g_dis[MAXN];
__device__ __align__(16) int   g_cnt[MAXN];
__device__ __align__(16) int   g_offs[MAXN + 1];
__device__ __align__(16) int   g_cur[MAXN];
__device__ __align__(16) int   g_adj[MAXE];
__device__ __align__(16) int   g_bsum[128];
__device__ __align__(16) float g_sums[NG_GRAPHS * 64];
__device__ __align__(16) float g_gcnt[NG_GRAPHS];

// ---------------------------------------------------------------------------
// count in-degrees; also zero pooling buffers (independent, saves launches)
// ---------------------------------------------------------------------------
__global__ void count_kernel(const int* __restrict__ dst, int* cnt,
                             float* sums, float* gcnt, int E) {
    int i = blockIdx.x * blockDim.x + threadIdx.x;
    if (i < E) atomicAdd(&cnt[dst[i]], 1);
    if (i < NG_GRAPHS * 64) sums[i] = 0.f;
    if (i < NG_GRAPHS) gcnt[i] = 0.f;
}

__global__ __launch_bounds__(SCAN_B) void scan_block_kernel(
    const int* __restrict__ cnt, int* offs, int* bsum, int N) {
    __shared__ int sh[SCAN_B];
    int t = threadIdx.x;
    int i = blockIdx.x * SCAN_B + t;
    int v = (i < N) ? cnt[i] : 0;
    sh[t] = v;
    __syncthreads();
#pragma unroll
    for (int off = 1; off < SCAN_B; off <<= 1) {
        int add = (t >= off) ? sh[t - off] : 0;
        __syncthreads();
        sh[t] += add;
        __syncthreads();
    }
    if (i < N) offs[i] = sh[t] - v;  // exclusive within tile
    if (t == SCAN_B - 1) bsum[blockIdx.x] = sh[t];  // tile total (raw)
}

// apply top-level scan (computed in-block over <=98 tile totals), finalize
// offs/cur, compute dis and xd = x*dis, and self-clear cnt for the next call.
__global__ __launch_bounds__(256) void scan_add_kernel(
    int* offs, const int* __restrict__ bsum, int* cur, int* cnt,
    const float* __restrict__ x, float* dis, float* xd, int N, int E) {
    __shared__ int base_sh;
    int tile = blockIdx.x >> 2;  // 256-thread block lies inside one 1024 tile
    if (threadIdx.x < 32) {
        int s = 0;
        for (int j = threadIdx.x; j < tile; j += 32) s += bsum[j];
#pragma unroll
        for (int o = 16; o; o >>= 1) s += __shfl_down_sync(0xFFFFFFFFu, s, o);
        if (threadIdx.x == 0) base_sh = s;
    }
    __syncthreads();
    int i = blockIdx.x * 256 + threadIdx.x;
    if (i < N) {
        int o = offs[i] + base_sh;
        offs[i] = o;
        cur[i] = o;
        float d = rsqrtf((float)cnt[i] + 1.0f);  // +1 self loop
        cnt[i] = 0;                              // reset for next call
        dis[i] = d;
        float4 v;
        v.x = x[i * 3 + 0] * d;
        v.y = x[i * 3 + 1] * d;
        v.z = x[i * 3 + 2] * d;
        v.w = 0.f;
        *(float4*)(xd + i * 4) = v;
    }
    if (i == 0) offs[N] = E;
}

// ---------------------------------------------------------------------------
// fused: CSR fill + W2/W3 transpose/split prep.
// Weight part reads COALESCED (consecutive threads -> consecutive output
// feature n), stores scattered (stores don't stall).
// ---------------------------------------------------------------------------
__global__ void fill_prep_kernel(const int* __restrict__ src, const int* __restrict__ dst,
                                 int* cur, int* adj, int E,
                                 const float* __restrict__ W2, const float* __restrict__ W3,
                                 __nv_bfloat16* bh2, __nv_bfloat16* bl2,
                                 __nv_bfloat16* bh3, __nv_bfloat16* bl3) {
    int i = blockIdx.x * blockDim.x + threadIdx.x;
    if (i < E) {
        int slot = atomicAdd(&cur[dst[i]], 1);
        adj[slot] = src[i];
        return;
    }
    int k = i - E;
    if (k < 128 * 128) {
        int kk = k >> 7, n = k & 127;            // coalesced read of W2 row kk
        float w = W2[kk * 128 + n];
        __nv_bfloat16 hi = __float2bfloat16_rn(w);
        __nv_bfloat16 lo = __float2bfloat16_rn(w - __bfloat162float(hi));
        bh2[n * 128 + kk] = hi;                  // scattered store
        bl2[n * 128 + kk] = lo;
    } else if (k < 128 * 128 + 64 * 128) {
        int j = k - 128 * 128;
        int kk = j >> 6, n = j & 63;             // coalesced read of W3 row kk
        float w = W3[kk * 64 + n];
        __nv_bfloat16 hi = __float2bfloat16_rn(w);
        __nv_bfloat16 lo = __float2bfloat16_rn(w - __bfloat162float(hi));
        bh3[n * 128 + kk] = hi;
        bl3[n * 128 + kk] = lo;
    }
}

// ---------------------------------------------------------------------------
// fused layer 1: warp per node.
//   z = xd[n] + sum_{s in adj(n)} xd[s]   (lane-strided + shfl reduce)
//   h[n] = relu(dis[n] * (z @ W1) + b1)   (lane -> 4 features)
// ---------------------------------------------------------------------------
__global__ __launch_bounds__(256) void l1_fused_kernel(
    const int* __restrict__ offs, const int* __restrict__ adj,
    const float* __restrict__ xd, const float* __restrict__ W1,
    const float* __restrict__ dis, const float* __restrict__ b1,
    float* __restrict__ h, int N) {
    __shared__ float ws[3 * 128];
    __shared__ float bs[128];
    for (int i = threadIdx.x; i < 384; i += blockDim.x) ws[i] = W1[i];
    for (int i = threadIdx.x; i < 128; i += blockDim.x) bs[i] = b1[i];
    __syncthreads();
    int node = (blockIdx.x * 256 + threadIdx.x) >> 5;
    int lane = threadIdx.x & 31;
    if (node >= N) return;
    int beg = offs[node];
    int end = offs[node + 1];
    const float4* xv = (const float4*)xd;
    float sx = 0.f, sy = 0.f, sz = 0.f;
    for (int e = beg + lane; e < end; e += 32) {
        int a = __ldg(&adj[e]);
        float4 v = __ldg(&xv[a]);
        sx += v.x; sy += v.y; sz += v.z;
    }
#pragma unroll
    for (int o = 16; o; o >>= 1) {
        sx += __shfl_xor_sync(0xFFFFFFFFu, sx, o);
        sy += __shfl_xor_sync(0xFFFFFFFFu, sy, o);
        sz += __shfl_xor_sync(0xFFFFFFFFu, sz, o);
    }
    float4 self = __ldg(&xv[node]);
    sx += self.x; sy += self.y; sz += self.z;
    float d = dis[node];
    int f = lane * 4;
    float4 o;
    o.x = fmaxf(fmaf(sx * ws[f + 0] + sy * ws[128 + f + 0] + sz * ws[256 + f + 0], d, bs[f + 0]), 0.f);
    o.y = fmaxf(fmaf(sx * ws[f + 1] + sy * ws[128 + f + 1] + sz * ws[256 + f + 1], d, bs[f + 1]), 0.f);
    o.z = fmaxf(fmaf(sx * ws[f + 2] + sy * ws[128 + f + 2] + sz * ws[256 + f + 2], d, bs[f + 2]), 0.f);
    o.w = fmaxf(fmaf(sx * ws[f + 3] + sy * ws[128 + f + 3] + sz * ws[256 + f + 3], d, bs[f + 3]), 0.f);
    *(float4*)(h + (size_t)node * 128 + f) = o;
}

// ---------------------------------------------------------------------------
// bf16x3 tensor-core GEMM via mma.sync.m16n8k16 (legacy HMMA, sm_103-safe):
//   out[n] = fp16( (A[n] @ W) * dis[n] ),  D = Ahi*Bhi + Alo*Bhi + Ahi*Blo.
// A input fp32 (exact hi/lo split); output stored fp16 (gather payload).
// Block = 256 thr (8 warps), tile = 128 rows x F. K staged in 2 chunks of 64.
// ---------------------------------------------------------------------------
#define LDH 72  // halfs per smem row (64 + 8 pad)

template <int F>
__global__ __launch_bounds__(256) void gemm_mma_kernel(
    const float* __restrict__ A, const __nv_bfloat16* __restrict__ Bhg,
    const __nv_bfloat16* __restrict__ Blg, const float* __restrict__ dis,
    __half* __restrict__ out, int N) {
    extern __shared__ __align__(16) __nv_bfloat16 smh[];
    __nv_bfloat16* Ah = smh;             // 128 x LDH
    __nv_bfloat16* Al = Ah + 128 * LDH;  // 128 x LDH
    __nv_bfloat16* Bh = Al + 128 * LDH;  // F x LDH
    __nv_bfloat16* Bl = Bh + F * LDH;    // F x LDH

    const int tid = threadIdx.x;
    const int warp = tid >> 5;
    const int lane = tid & 31;
    const int g = lane >> 2;   // 0..7
    const int tg = lane & 3;   // 0..3
    const int n0 = blockIdx.x * 128;

    constexpr int NT = F / 8;
    float acc[NT][4];
#pragma unroll
    for (int i = 0; i < NT; i++) {
        acc[i][0] = acc[i][1] = acc[i][2] = acc[i][3] = 0.f;
    }

    for (int kc = 0; kc < 128; kc += 64) {
        __syncthreads();  // protect smem from previous chunk's readers
        // stage A chunk [128 x 64] with bf16 hi/lo split
        for (int i = tid; i < 128 * 16; i += 256) {
            int r = i >> 4, c4 = i & 15;
            float4 v = make_float4(0.f, 0.f, 0.f, 0.f);
            int n = n0 + r;
            if (n < N) v = *(const float4*)(A + (size_t)n * 128 + kc + c4 * 4);
            __nv_bfloat16 h0 = __float2bfloat16_rn(v.x);
            __nv_bfloat16 h1 = __float2bfloat16_rn(v.y);
            __nv_bfloat16 h2 = __float2bfloat16_rn(v.z);
            __nv_bfloat16 h3 = __float2bfloat16_rn(v.w);
            __nv_bfloat162 hp0 = {h0, h1}, hp1 = {h2, h3};
            __nv_bfloat162 lp0 = {__float2bfloat16_rn(v.x - __bfloat162float(h0)),
                                  __float2bfloat16_rn(v.y - __bfloat162float(h1))};
            __nv_bfloat162 lp1 = {__float2bfloat16_rn(v.z - __bfloat162float(h2)),
                                  __float2bfloat16_rn(v.w - __bfloat162float(h3))};
            uint2 hu, lu;
            hu.x = *(uint32_t*)&hp0; hu.y = *(uint32_t*)&hp1;
            lu.x = *(uint32_t*)&lp0; lu.y = *(uint32_t*)&lp1;
            *(uint2*)(Ah + r * LDH + c4 * 4) = hu;
            *(uint2*)(Al + r * LDH + c4 * 4) = lu;
        }
        // stage B chunk [F x 64] (already bf16 hi/lo in global, n-major)
        for (int i = tid; i < F * 8; i += 256) {
            int r = i >> 3, c8 = i & 7;
            *(uint4*)(Bh + r * LDH + c8 * 8) = *(const uint4*)(Bhg + r * 128 + kc + c8 * 8);
            *(uint4*)(Bl + r * LDH + c8 * 8) = *(const uint4*)(Blg + r * 128 + kc + c8 * 8);
        }
        __syncthreads();

        const __nv_bfloat16* ar0 = Ah + (warp * 16 + g) * LDH + 2 * tg;
        const __nv_bfloat16* al0 = Al + (warp * 16 + g) * LDH + 2 * tg;
#pragma unroll
        for (int ks = 0; ks < 4; ks++) {
            const int ko = ks * 16;
            uint32_t ah0 = *(const uint32_t*)(ar0 + ko);
            uint32_t ah1 = *(const uint32_t*)(ar0 + 8 * LDH + ko);
            uint32_t ah2 = *(const uint32_t*)(ar0 + ko + 8);
            uint32_t ah3 = *(const uint32_t*)(ar0 + 8 * LDH + ko + 8);
            uint32_t aw0 = *(const uint32_t*)(al0 + ko);
            uint32_t aw1 = *(const uint32_t*)(al0 + 8 * LDH + ko);
            uint32_t aw2 = *(const uint32_t*)(al0 + ko + 8);
            uint32_t aw3 = *(const uint32_t*)(al0 + 8 * LDH + ko + 8);
#pragma unroll
            for (int nt = 0; nt < NT; nt++) {
                const __nv_bfloat16* bhr = Bh + (nt * 8 + g) * LDH + 2 * tg + ko;
                const __nv_bfloat16* blr = Bl + (nt * 8 + g) * LDH + 2 * tg + ko;
                uint32_t bh0 = *(const uint32_t*)bhr;
                uint32_t bh1 = *(const uint32_t*)(bhr + 8);
                uint32_t bl0 = *(const uint32_t*)blr;
                uint32_t bl1 = *(const uint32_t*)(blr + 8);
                asm volatile(
                    "mma.sync.aligned.m16n8k16.row.col.f32.bf16.bf16.f32 "
                    "{%0,%1,%2,%3}, {%4,%5,%6,%7}, {%8,%9}, {%0,%1,%2,%3};"
                    : "+f"(acc[nt][0]), "+f"(acc[nt][1]), "+f"(acc[nt][2]), "+f"(acc[nt][3])
                    : "r"(ah0), "r"(ah1), "r"(ah2), "r"(ah3), "r"(bh0), "r"(bh1));
                asm volatile(
                    "mma.sync.aligned.m16n8k16.row.col.f32.bf16.bf16.f32 "
                    "{%0,%1,%2,%3}, {%4,%5,%6,%7}, {%8,%9}, {%0,%1,%2,%3};"
                    : "+f"(acc[nt][0]), "+f"(acc[nt][1]), "+f"(acc[nt][2]), "+f"(acc[nt][3])
                    : "r"(aw0), "r"(aw1), "r"(aw2), "r"(aw3), "r"(bh0), "r"(bh1));
                asm volatile(
                    "mma.sync.aligned.m16n8k16.row.col.f32.bf16.bf16.f32 "
                    "{%0,%1,%2,%3}, {%4,%5,%6,%7}, {%8,%9}, {%0,%1,%2,%3};"
                    : "+f"(acc[nt][0]), "+f"(acc[nt][1]), "+f"(acc[nt][2]), "+f"(acc[nt][3])
                    : "r"(ah0), "r"(ah1), "r"(ah2), "r"(ah3), "r"(bl0), "r"(bl1));
            }
        }
    }

    // epilogue: x dis, fp16 store. c0,c1 = row g cols 2tg,2tg+1; c2,c3 = g+8.
    int m0 = n0 + warp * 16 + g;
    int m1 = m0 + 8;
    float d0 = (m0 < N) ? dis[m0] : 0.f;
    float d1 = (m1 < N) ? dis[m1] : 0.f;
#pragma unroll
    for (int nt = 0; nt < NT; nt++) {
        if (m0 < N) {
            __half2 o = __floats2half2_rn(acc[nt][0] * d0, acc[nt][1] * d0);
            *(__half2*)(out + (size_t)m0 * F + nt * 8 + tg * 2) = o;
        }
        if (m1 < N) {
            __half2 o = __floats2half2_rn(acc[nt][2] * d1, acc[nt][3] * d1);
            *(__half2*)(out + (size_t)m1 * F + nt * 8 + tg * 2) = o;
        }
    }
}

// ---------------------------------------------------------------------------
// CSR gather + epilogue: h[d] = relu(dis[d]*(sum_{s in adj(d)} t[s] + t[d]) + b)
// One warp per dst node; fp16 payload, fp32 accumulation, fp32 h out.
// ---------------------------------------------------------------------------
template <int F>
__global__ __launch_bounds__(256) void gather_kernel(
    const int* __restrict__ offs, const int* __restrict__ adj,
    const __half* __restrict__ t, const float* __restrict__ dis,
    const float* __restrict__ b, float* __restrict__ h, int N) {
    int node = (blockIdx.x * 256 + threadIdx.x) >> 5;
    int lane = threadIdx.x & 31;
    if (node >= N) return;
    int beg = offs[node];
    int end = offs[node + 1];
    float d = dis[node];
    if constexpr (F == 128) {
        const uint2* tv = (const uint2*)t;  // 4 halfs per elem; 32 per row
        uint2 raw = __ldg(&tv[(size_t)node * 32 + lane]);  // self loop
        float2 f0 = __half22float2(*(__half2*)&raw.x);
        float2 f1 = __half22float2(*(__half2*)&raw.y);
        float s0 = f0.x, s1 = f0.y, s2 = f1.x, s3 = f1.y;
        float u0 = 0.f, u1 = 0.f, u2 = 0.f, u3 = 0.f;
        int e = beg;
        for (; e + 4 <= end; e += 4) {
            int a0 = __ldg(&adj[e]);
            int a1 = __ldg(&adj[e + 1]);
            int a2 = __ldg(&adj[e + 2]);
            int a3 = __ldg(&adj[e + 3]);
            uint2 r0 = __ldg(&tv[(size_t)a0 * 32 + lane]);
            uint2 r1 = __ldg(&tv[(size_t)a1 * 32 + lane]);
            uint2 r2 = __ldg(&tv[(size_t)a2 * 32 + lane]);
            uint2 r3 = __ldg(&tv[(size_t)a3 * 32 + lane]);
            float2 x0 = __half22float2(*(__half2*)&r0.x);
            float2 x1 = __half22float2(*(__half2*)&r0.y);
            float2 y0 = __half22float2(*(__half2*)&r1.x);
            float2 y1 = __half22float2(*(__half2*)&r1.y);
            float2 z0 = __half22float2(*(__half2*)&r2.x);
            float2 z1 = __half22float2(*(__half2*)&r2.y);
            float2 w0 = __half22float2(*(__half2*)&r3.x);
            float2 w1 = __half22float2(*(__half2*)&r3.y);
            s0 += x0.x + z0.x; s1 += x0.y + z0.y;
            s2 += x1.x + z1.x; s3 += x1.y + z1.y;
            u0 += y0.x + w0.x; u1 += y0.y + w0.y;
            u2 += y1.x + w1.x; u3 += y1.y + w1.y;
        }
        for (; e < end; e++) {
            int a = __ldg(&adj[e]);
            uint2 r0 = __ldg(&tv[(size_t)a * 32 + lane]);
            float2 x0 = __half22float2(*(__half2*)&r0.x);
            float2 x1 = __half22float2(*(__half2*)&r0.y);
            s0 += x0.x; s1 += x0.y; s2 += x1.x; s3 += x1.y;
        }
        float4 bv = __ldg(&((const float4*)b)[lane]);
        float4 o;
        o.x = fmaxf(fmaf(s0 + u0, d, bv.x), 0.f);
        o.y = fmaxf(fmaf(s1 + u1, d, bv.y), 0.f);
        o.z = fmaxf(fmaf(s2 + u2, d, bv.z), 0.f);
        o.w = fmaxf(fmaf(s3 + u3, d, bv.w), 0.f);
        ((float4*)h)[(size_t)node * 32 + lane] = o;
    } else {
        const uint32_t* tv = (const uint32_t*)t;  // 2 halfs; 32 per row
        uint32_t raw = __ldg(&tv[(size_t)node * 32 + lane]);  // self loop
        float2 f0 = __half22float2(*(__half2*)&raw);
        float s0 = f0.x, s1 = f0.y;
        float u0 = 0.f, u1 = 0.f;
        int e = beg;
        for (; e + 4 <= end; e += 4) {
            int a0 = __ldg(&adj[e]);
            int a1 = __ldg(&adj[e + 1]);
            int a2 = __ldg(&adj[e + 2]);
            int a3 = __ldg(&adj[e + 3]);
            uint32_t r0 = __ldg(&tv[(size_t)a0 * 32 + lane]);
            uint32_t r1 = __ldg(&tv[(size_t)a1 * 32 + lane]);
            uint32_t r2 = __ldg(&tv[(size_t)a2 * 32 + lane]);
            uint32_t r3 = __ldg(&tv[(size_t)a3 * 32 + lane]);
            float2 x0 = __half22float2(*(__half2*)&r0);
            float2 y0 = __half22float2(*(__half2*)&r1);
            float2 z0 = __half22float2(*(__half2*)&r2);
            float2 w0 = __half22float2(*(__half2*)&r3);
            s0 += x0.x + z0.x; s1 += x0.y + z0.y;
            u0 += y0.x + w0.x; u1 += y0.y + w0.y;
        }
        for (; e < end; e++) {
            int a = __ldg(&adj[e]);
            uint32_t r0 = __ldg(&tv[(size_t)a * 32 + lane]);
            float2 x0 = __half22float2(*(__half2*)&r0);
            s0 += x0.x; s1 += x0.y;
        }
        float2 bv = __ldg(&((const float2*)b)[lane]);
        float2 o;
        o.x = fmaxf(fmaf(s0 + u0, d, bv.x), 0.f);
        o.y = fmaxf(fmaf(s1 + u1, d, bv.y), 0.f);
        ((float2*)h)[(size_t)node * 32 + lane] = o;
    }
}

// ---------------------------------------------------------------------------
// pooling: batch sorted -> segmented reduction. Block = 256 thr = 4 groups of
// 64 features; each group reduces a 64-node segment.
// ---------------------------------------------------------------------------
__global__ __launch_bounds__(256) void pool_kernel(
    const float* __restrict__ h, const int* __restrict__ batch,
    float* __restrict__ sums, float* __restrict__ cnt, int N) {
    int grp = threadIdx.x >> 6;
    int f = threadIdx.x & 63;
    int start = blockIdx.x * 256 + grp * 64;
    if (start >= N) return;
    int end = min(start + 64, N);
    int g = batch[start];
    float s = 0.f, c = 0.f;
    for (int n = start; n < end; n++) {
        int bn = batch[n];
        if (bn != g) {
            atomicAdd(&sums[g * 64 + f], s);
            if (f == 0) atomicAdd(&cnt[g], c);
            s = 0.f; c = 0.f; g = bn;
        }
        s += h[(size_t)n * 64 + f];
        c += 1.f;
    }
    atomicAdd(&sums[g * 64 + f], s);
    if (f == 0) atomicAdd(&cnt[g], c);
}

__global__ void final_kernel(const float* __restrict__ sums, const float* __restrict__ cnt,
                             const float* __restrict__ Wl, const float* __restrict__ bl,
                             float* __restrict__ out) {
    int g = blockIdx.x * blockDim.x + threadIdx.x;
    if (g >= NG_GRAPHS) return;
    float c = fmaxf(cnt[g], 1.0f);
    float acc = 0.f;
#pragma unroll
    for (int f = 0; f < 64; f++) acc = fmaf(sums[g * 64 + f], Wl[f], acc);
    out[g] = acc / c + bl[0];
}

// ---------------------------------------------------------------------------
extern "C" void kernel_launch(void* const* d_in, const int* in_sizes, int n_in,
                              void* d_out, int out_size) {
    const float* x     = (const float*)d_in[0];
    const int*   ei    = (const int*)d_in[1];    // int32
    const int*   batch = (const int*)d_in[2];    // int32
    const float* W1 = (const float*)d_in[3];
    const float* b1 = (const float*)d_in[4];
    const float* W2 = (const float*)d_in[5];
    const float* b2 = (const float*)d_in[6];
    const float* W3 = (const float*)d_in[7];
    const float* b3 = (const float*)d_in[8];
    const float* Wl = (const float*)d_in[9];
    const float* bl = (const float*)d_in[10];
    float* out = (float*)d_out;

    const int N = in_sizes[0] / 3;
    const int E = in_sizes[1] / 2;
    const int* srcp = ei;
    const int* dstp = ei + E;

    float *h, *xd, *dis, *sums, *gcnt;
    __half* t;
    __nv_bfloat16 *bh2, *bl2, *bh3, *bl3;
    int *cnt, *offs, *cur, *adj, *bsum;
    cudaGetSymbolAddress((void**)&t, g_t);
    cudaGetSymbolAddress((void**)&h, g_h);
    cudaGetSymbolAddress((void**)&xd, g_xd);
    cudaGetSymbolAddress((void**)&bh2, g_bh2);
    cudaGetSymbolAddress((void**)&bl2, g_bl2);
    cudaGetSymbolAddress((void**)&bh3, g_bh3);
    cudaGetSymbolAddress((void**)&bl3, g_bl3);
    cudaGetSymbolAddress((void**)&dis, g_dis);
    cudaGetSymbolAddress((void**)&cnt, g_cnt);
    cudaGetSymbolAddress((void**)&offs, g_offs);
    cudaGetSymbolAddress((void**)&cur, g_cur);
    cudaGetSymbolAddress((void**)&adj, g_adj);
    cudaGetSymbolAddress((void**)&bsum, g_bsum);
    cudaGetSymbolAddress((void**)&sums, g_sums);
    cudaGetSymbolAddress((void**)&gcnt, g_gcnt);

    // smem: (128 A rows hi+lo + F B rows hi+lo) x LDH halfs
    const int SMEM128 = (2 * 128 + 2 * 128) * LDH * 2;  // 73,728 B
    const int SMEM64  = (2 * 128 + 2 * 64) * LDH * 2;   // 55,296 B
    cudaFuncSetAttribute(gemm_mma_kernel<128>,
                         cudaFuncAttributeMaxDynamicSharedMemorySize, SMEM128);
    cudaFuncSetAttribute(gemm_mma_kernel<64>,
                         cudaFuncAttributeMaxDynamicSharedMemorySize, SMEM64);

    const int nB = (N + 255) / 256;
    const int eB = (E + 255) / 256;
    const int NB_SCAN = (N + SCAN_B - 1) / SCAN_B;
    const int wB = (N * 32 + 255) / 256;      // warp-per-node grids
    const int gB = (N + 127) / 128;           // gemm grids
    const int fpB = (E + 128 * 128 + 64 * 128 + 255) / 256;

    // --- CSR build + prep (cnt is zero at entry: zero-init on call 1, ---
    // --- self-cleared by scan_add on every call)                      ---
    count_kernel<<<eB, 256>>>(dstp, cnt, sums, gcnt, E);
    scan_block_kernel<<<NB_SCAN, SCAN_B>>>(cnt, offs, bsum, N);
    scan_add_kernel<<<nB, 256>>>(offs, bsum, cur, cnt, x, dis, xd, N, E);
    fill_prep_kernel<<<fpB, 256>>>(srcp, dstp, cur, adj, E,
                                   W2, W3, bh2, bl2, bh3, bl3);

    // --- layer 1 (3 -> 128): fused aggregate + transform ---
    l1_fused_kernel<<<wB, 256>>>(offs, adj, xd, W1, dis, b1, h, N);

    // --- layer 2 (128 -> 128) ---
    gemm_mma_kernel<128><<<gB, 256, SMEM128>>>(h, bh2, bl2, dis, t, N);
    gather_kernel<128><<<wB, 256>>>(offs, adj, t, dis, b2, h, N);

    // --- layer 3 (128 -> 64) ---
    gemm_mma_kernel<64><<<gB, 256, SMEM64>>>(h, bh3, bl3, dis, t, N);
    gather_kernel<64><<<wB, 256>>>(offs, adj, t, dis, b3, h, N);

    // --- pooling + final linear ---
    pool_kernel<<<nB, 256>>>(h, batch, sums, gcnt, N);
    final_kernel<<<2, 256>>>(sums, gcnt, Wl, bl, out);
}

// round 11
// speedup vs baseline: 2.1926x; 1.1006x over previous
#include <cuda_runtime.h>
#include <cuda_bf16.h>
#include <cuda_fp16.h>
#include <cstdint>

#define MAXN 100000
#define MAXE 600000
#define NG_GRAPHS 512
#define SCAN_B 1024

// Scratch (static device globals; allocation-free).
// NOTE: g_cnt relies on (a) CUDA zero-init of device globals for the first
// call, (b) scan_add_kernel re-zeroing it at the end of every call.
__device__ __align__(16) __half g_t[MAXN * 128];   // fp16 GEMM output (gather payload)
__device__ __align__(16) __half g_h[MAXN * 128];   // fp16 activations
__device__ __align__(16) float g_xd[MAXN * 4];     // x * dis, padded float4
__device__ __align__(16) __nv_bfloat16 g_bh2[128 * 128];  // W2^T hi (n-major [n][k])
__device__ __align__(16) __nv_bfloat16 g_bl2[128 * 128];  // W2^T lo
__device__ __align__(16) __nv_bfloat16 g_bh3[64 * 128];   // W3^T hi
__device__ __align__(16) __nv_bfloat16 g_bl3[64 * 128];   // W3^T lo
__device__ __align__(16) float g_dis[MAXN];
__device__ __align__(16) int   g_cnt[MAXN];
__device__ __align__(16) int   g_offs[MAXN + 1];
__device__ __align__(16) int   g_cur[MAXN];
__device__ __align__(16) int   g_adj[MAXE];
__device__ __align__(16) int   g_bsum[128];
__device__ __align__(16) float g_sums[NG_GRAPHS * 64];
__device__ __align__(16) float g_gcnt[NG_GRAPHS];

// ---------------------------------------------------------------------------
// count in-degrees; also zero pooling buffers (independent, saves launches)
// ---------------------------------------------------------------------------
__global__ void count_kernel(const int* __restrict__ dst, int* cnt,
                             float* sums, float* gcnt, int E) {
    int i = blockIdx.x * blockDim.x + threadIdx.x;
    if (i < E) atomicAdd(&cnt[dst[i]], 1);
    if (i < NG_GRAPHS * 64) sums[i] = 0.f;
    if (i < NG_GRAPHS) gcnt[i] = 0.f;
}

__global__ __launch_bounds__(SCAN_B) void scan_block_kernel(
    const int* __restrict__ cnt, int* offs, int* bsum, int N) {
    __shared__ int sh[SCAN_B];
    int t = threadIdx.x;
    int i = blockIdx.x * SCAN_B + t;
    int v = (i < N) ? cnt[i] : 0;
    sh[t] = v;
    __syncthreads();
#pragma unroll
    for (int off = 1; off < SCAN_B; off <<= 1) {
        int add = (t >= off) ? sh[t - off] : 0;
        __syncthreads();
        sh[t] += add;
        __syncthreads();
    }
    if (i < N) offs[i] = sh[t] - v;  // exclusive within tile
    if (t == SCAN_B - 1) bsum[blockIdx.x] = sh[t];  // tile total (raw)
}

// apply top-level scan (computed in-block over <=98 tile totals), finalize
// offs/cur, compute dis and xd = x*dis, and self-clear cnt for the next call.
__global__ __launch_bounds__(256) void scan_add_kernel(
    int* offs, const int* __restrict__ bsum, int* cur, int* cnt,
    const float* __restrict__ x, float* dis, float* xd, int N, int E) {
    __shared__ int base_sh;
    int tile = blockIdx.x >> 2;  // 256-thread block lies inside one 1024 tile
    if (threadIdx.x < 32) {
        int s = 0;
        for (int j = threadIdx.x; j < tile; j += 32) s += bsum[j];
#pragma unroll
        for (int o = 16; o; o >>= 1) s += __shfl_down_sync(0xFFFFFFFFu, s, o);
        if (threadIdx.x == 0) base_sh = s;
    }
    __syncthreads();
    int i = blockIdx.x * 256 + threadIdx.x;
    if (i < N) {
        int o = offs[i] + base_sh;
        offs[i] = o;
        cur[i] = o;
        float d = rsqrtf((float)cnt[i] + 1.0f);  // +1 self loop
        cnt[i] = 0;                              // reset for next call
        dis[i] = d;
        float4 v;
        v.x = x[i * 3 + 0] * d;
        v.y = x[i * 3 + 1] * d;
        v.z = x[i * 3 + 2] * d;
        v.w = 0.f;
        *(float4*)(xd + i * 4) = v;
    }
    if (i == 0) offs[N] = E;
}

// ---------------------------------------------------------------------------
// fused: CSR fill + W2/W3 transpose/split prep (coalesced weight reads)
// ---------------------------------------------------------------------------
__global__ void fill_prep_kernel(const int* __restrict__ src, const int* __restrict__ dst,
                                 int* cur, int* adj, int E,
                                 const float* __restrict__ W2, const float* __restrict__ W3,
                                 __nv_bfloat16* bh2, __nv_bfloat16* bl2,
                                 __nv_bfloat16* bh3, __nv_bfloat16* bl3) {
    int i = blockIdx.x * blockDim.x + threadIdx.x;
    if (i < E) {
        int slot = atomicAdd(&cur[dst[i]], 1);
        adj[slot] = src[i];
        return;
    }
    int k = i - E;
    if (k < 128 * 128) {
        int kk = k >> 7, n = k & 127;            // coalesced read of W2 row kk
        float w = W2[kk * 128 + n];
        __nv_bfloat16 hi = __float2bfloat16_rn(w);
        __nv_bfloat16 lo = __float2bfloat16_rn(w - __bfloat162float(hi));
        bh2[n * 128 + kk] = hi;                  // scattered store
        bl2[n * 128 + kk] = lo;
    } else if (k < 128 * 128 + 64 * 128) {
        int j = k - 128 * 128;
        int kk = j >> 6, n = j & 63;             // coalesced read of W3 row kk
        float w = W3[kk * 64 + n];
        __nv_bfloat16 hi = __float2bfloat16_rn(w);
        __nv_bfloat16 lo = __float2bfloat16_rn(w - __bfloat162float(hi));
        bh3[n * 128 + kk] = hi;
        bl3[n * 128 + kk] = lo;
    }
}

// ---------------------------------------------------------------------------
// fused layer 1: warp per node.
//   z = xd[n] + sum_{s in adj(n)} xd[s]   (lane-strided + shfl reduce)
//   h[n] = fp16( relu(dis[n] * (z @ W1) + b1) )
// ---------------------------------------------------------------------------
__global__ __launch_bounds__(256) void l1_fused_kernel(
    const int* __restrict__ offs, const int* __restrict__ adj,
    const float* __restrict__ xd, const float* __restrict__ W1,
    const float* __restrict__ dis, const float* __restrict__ b1,
    __half* __restrict__ h, int N) {
    __shared__ float ws[3 * 128];
    __shared__ float bs[128];
    for (int i = threadIdx.x; i < 384; i += blockDim.x) ws[i] = W1[i];
    for (int i = threadIdx.x; i < 128; i += blockDim.x) bs[i] = b1[i];
    __syncthreads();
    int node = (blockIdx.x * 256 + threadIdx.x) >> 5;
    int lane = threadIdx.x & 31;
    if (node >= N) return;
    int beg = offs[node];
    int end = offs[node + 1];
    const float4* xv = (const float4*)xd;
    float sx = 0.f, sy = 0.f, sz = 0.f;
    for (int e = beg + lane; e < end; e += 32) {
        int a = __ldg(&adj[e]);
        float4 v = __ldg(&xv[a]);
        sx += v.x; sy += v.y; sz += v.z;
    }
#pragma unroll
    for (int o = 16; o; o >>= 1) {
        sx += __shfl_xor_sync(0xFFFFFFFFu, sx, o);
        sy += __shfl_xor_sync(0xFFFFFFFFu, sy, o);
        sz += __shfl_xor_sync(0xFFFFFFFFu, sz, o);
    }
    float4 self = __ldg(&xv[node]);
    sx += self.x; sy += self.y; sz += self.z;
    float d = dis[node];
    int f = lane * 4;
    float o0 = fmaxf(fmaf(sx * ws[f + 0] + sy * ws[128 + f + 0] + sz * ws[256 + f + 0], d, bs[f + 0]), 0.f);
    float o1 = fmaxf(fmaf(sx * ws[f + 1] + sy * ws[128 + f + 1] + sz * ws[256 + f + 1], d, bs[f + 1]), 0.f);
    float o2 = fmaxf(fmaf(sx * ws[f + 2] + sy * ws[128 + f + 2] + sz * ws[256 + f + 2], d, bs[f + 2]), 0.f);
    float o3 = fmaxf(fmaf(sx * ws[f + 3] + sy * ws[128 + f + 3] + sz * ws[256 + f + 3], d, bs[f + 3]), 0.f);
    __half2 q0 = __floats2half2_rn(o0, o1);
    __half2 q1 = __floats2half2_rn(o2, o3);
    uint2 pk;
    pk.x = *(unsigned*)&q0;
    pk.y = *(unsigned*)&q1;
    *(uint2*)(h + (size_t)node * 128 + f) = pk;
}

// ---------------------------------------------------------------------------
// bf16x3 tensor-core GEMM via mma.sync.m16n8k16 (legacy HMMA, sm_103-safe):
//   out[n] = fp16( (A[n] @ W) * dis[n] ),  D = Ahi*Bhi + Alo*Bhi + Ahi*Blo.
// A input fp16 (bf16 hi/lo split is EXACT for fp16 values); out fp16.
// Block = 256 thr (8 warps), tile = 128 rows x F. K staged in 2 chunks of 64.
// ---------------------------------------------------------------------------
#define LDH 72  // halfs per smem row (64 + 8 pad)

template <int F>
__global__ __launch_bounds__(256) void gemm_mma_kernel(
    const __half* __restrict__ A, const __nv_bfloat16* __restrict__ Bhg,
    const __nv_bfloat16* __restrict__ Blg, const float* __restrict__ dis,
    __half* __restrict__ out, int N) {
    extern __shared__ __align__(16) __nv_bfloat16 smh[];
    __nv_bfloat16* Ah = smh;             // 128 x LDH
    __nv_bfloat16* Al = Ah + 128 * LDH;  // 128 x LDH
    __nv_bfloat16* Bh = Al + 128 * LDH;  // F x LDH
    __nv_bfloat16* Bl = Bh + F * LDH;    // F x LDH

    const int tid = threadIdx.x;
    const int warp = tid >> 5;
    const int lane = tid & 31;
    const int g = lane >> 2;   // 0..7
    const int tg = lane & 3;   // 0..3
    const int n0 = blockIdx.x * 128;

    constexpr int NT = F / 8;
    float acc[NT][4];
#pragma unroll
    for (int i = 0; i < NT; i++) {
        acc[i][0] = acc[i][1] = acc[i][2] = acc[i][3] = 0.f;
    }

    for (int kc = 0; kc < 128; kc += 64) {
        __syncthreads();  // protect smem from previous chunk's readers
        // stage A chunk [128 x 64] fp16 -> bf16 hi/lo split (exact)
        for (int i = tid; i < 128 * 8; i += 256) {
            int r = i >> 3, c8 = i & 7;           // 8 halfs per thread-iter
            uint4 raw = make_uint4(0u, 0u, 0u, 0u);
            int n = n0 + r;
            if (n < N) raw = *(const uint4*)(A + (size_t)n * 128 + kc + c8 * 8);
            const __half2* hp = (const __half2*)&raw;
            uint4 hu, lu;
            uint32_t* hw = (uint32_t*)&hu;
            uint32_t* lw = (uint32_t*)&lu;
#pragma unroll
            for (int q = 0; q < 4; q++) {
                float2 fv = __half22float2(hp[q]);
                __nv_bfloat16 h0 = __float2bfloat16_rn(fv.x);
                __nv_bfloat16 h1 = __float2bfloat16_rn(fv.y);
                __nv_bfloat162 hh = {h0, h1};
                __nv_bfloat162 ll = {__float2bfloat16_rn(fv.x - __bfloat162float(h0)),
                                     __float2bfloat16_rn(fv.y - __bfloat162float(h1))};
                hw[q] = *(uint32_t*)&hh;
                lw[q] = *(uint32_t*)&ll;
            }
            *(uint4*)(Ah + r * LDH + c8 * 8) = hu;
            *(uint4*)(Al + r * LDH + c8 * 8) = lu;
        }
        // stage B chunk [F x 64] (already bf16 hi/lo in global, n-major)
        for (int i = tid; i < F * 8; i += 256) {
            int r = i >> 3, c8 = i & 7;
            *(uint4*)(Bh + r * LDH + c8 * 8) = *(const uint4*)(Bhg + r * 128 + kc + c8 * 8);
            *(uint4*)(Bl + r * LDH + c8 * 8) = *(const uint4*)(Blg + r * 128 + kc + c8 * 8);
        }
        __syncthreads();

        const __nv_bfloat16* ar0 = Ah + (warp * 16 + g) * LDH + 2 * tg;
        const __nv_bfloat16* al0 = Al + (warp * 16 + g) * LDH + 2 * tg;
#pragma unroll
        for (int ks = 0; ks < 4; ks++) {
            const int ko = ks * 16;
            uint32_t ah0 = *(const uint32_t*)(ar0 + ko);
            uint32_t ah1 = *(const uint32_t*)(ar0 + 8 * LDH + ko);
            uint32_t ah2 = *(const uint32_t*)(ar0 + ko + 8);
            uint32_t ah3 = *(const uint32_t*)(ar0 + 8 * LDH + ko + 8);
            uint32_t aw0 = *(const uint32_t*)(al0 + ko);
            uint32_t aw1 = *(const uint32_t*)(al0 + 8 * LDH + ko);
            uint32_t aw2 = *(const uint32_t*)(al0 + ko + 8);
            uint32_t aw3 = *(const uint32_t*)(al0 + 8 * LDH + ko + 8);
#pragma unroll
            for (int nt = 0; nt < NT; nt++) {
                const __nv_bfloat16* bhr = Bh + (nt * 8 + g) * LDH + 2 * tg + ko;
                const __nv_bfloat16* blr = Bl + (nt * 8 + g) * LDH + 2 * tg + ko;
                uint32_t bh0 = *(const uint32_t*)bhr;
                uint32_t bh1 = *(const uint32_t*)(bhr + 8);
                uint32_t bl0 = *(const uint32_t*)blr;
                uint32_t bl1 = *(const uint32_t*)(blr + 8);
                asm volatile(
                    "mma.sync.aligned.m16n8k16.row.col.f32.bf16.bf16.f32 "
                    "{%0,%1,%2,%3}, {%4,%5,%6,%7}, {%8,%9}, {%0,%1,%2,%3};"
                    : "+f"(acc[nt][0]), "+f"(acc[nt][1]), "+f"(acc[nt][2]), "+f"(acc[nt][3])
                    : "r"(ah0), "r"(ah1), "r"(ah2), "r"(ah3), "r"(bh0), "r"(bh1));
                asm volatile(
                    "mma.sync.aligned.m16n8k16.row.col.f32.bf16.bf16.f32 "
                    "{%0,%1,%2,%3}, {%4,%5,%6,%7}, {%8,%9}, {%0,%1,%2,%3};"
                    : "+f"(acc[nt][0]), "+f"(acc[nt][1]), "+f"(acc[nt][2]), "+f"(acc[nt][3])
                    : "r"(aw0), "r"(aw1), "r"(aw2), "r"(aw3), "r"(bh0), "r"(bh1));
                asm volatile(
                    "mma.sync.aligned.m16n8k16.row.col.f32.bf16.bf16.f32 "
                    "{%0,%1,%2,%3}, {%4,%5,%6,%7}, {%8,%9}, {%0,%1,%2,%3};"
                    : "+f"(acc[nt][0]), "+f"(acc[nt][1]), "+f"(acc[nt][2]), "+f"(acc[nt][3])
                    : "r"(ah0), "r"(ah1), "r"(ah2), "r"(ah3), "r"(bl0), "r"(bl1));
            }
        }
    }

    // epilogue: x dis, fp16 store. c0,c1 = row g cols 2tg,2tg+1; c2,c3 = g+8.
    int m0 = n0 + warp * 16 + g;
    int m1 = m0 + 8;
    float d0 = (m0 < N) ? dis[m0] : 0.f;
    float d1 = (m1 < N) ? dis[m1] : 0.f;
#pragma unroll
    for (int nt = 0; nt < NT; nt++) {
        if (m0 < N) {
            __half2 o = __floats2half2_rn(acc[nt][0] * d0, acc[nt][1] * d0);
            *(__half2*)(out + (size_t)m0 * F + nt * 8 + tg * 2) = o;
        }
        if (m1 < N) {
            __half2 o = __floats2half2_rn(acc[nt][2] * d1, acc[nt][3] * d1);
            *(__half2*)(out + (size_t)m1 * F + nt * 8 + tg * 2) = o;
        }
    }
}

// ---------------------------------------------------------------------------
// CSR gather + epilogue: h[d] = fp16(relu(dis[d]*(sum t[s] + t[d]) + b))
// One warp per dst node; fp16 payload, fp32 accumulation, fp16 h out.
// ---------------------------------------------------------------------------
template <int F>
__global__ __launch_bounds__(256) void gather_kernel(
    const int* __restrict__ offs, const int* __restrict__ adj,
    const __half* __restrict__ t, const float* __restrict__ dis,
    const float* __restrict__ b, __half* __restrict__ h, int N) {
    int node = (blockIdx.x * 256 + threadIdx.x) >> 5;
    int lane = threadIdx.x & 31;
    if (node >= N) return;
    int beg = offs[node];
    int end = offs[node + 1];
    float d = dis[node];
    if constexpr (F == 128) {
        const uint2* tv = (const uint2*)t;  // 4 halfs per elem; 32 per row
        uint2 raw = __ldg(&tv[(size_t)node * 32 + lane]);  // self loop
        float2 f0 = __half22float2(*(__half2*)&raw.x);
        float2 f1 = __half22float2(*(__half2*)&raw.y);
        float s0 = f0.x, s1 = f0.y, s2 = f1.x, s3 = f1.y;
        float u0 = 0.f, u1 = 0.f, u2 = 0.f, u3 = 0.f;
        int e = beg;
        for (; e + 4 <= end; e += 4) {
            int a0 = __ldg(&adj[e]);
            int a1 = __ldg(&adj[e + 1]);
            int a2 = __ldg(&adj[e + 2]);
            int a3 = __ldg(&adj[e + 3]);
            uint2 r0 = __ldg(&tv[(size_t)a0 * 32 + lane]);
            uint2 r1 = __ldg(&tv[(size_t)a1 * 32 + lane]);
            uint2 r2 = __ldg(&tv[(size_t)a2 * 32 + lane]);
            uint2 r3 = __ldg(&tv[(size_t)a3 * 32 + lane]);
            float2 x0 = __half22float2(*(__half2*)&r0.x);
            float2 x1 = __half22float2(*(__half2*)&r0.y);
            float2 y0 = __half22float2(*(__half2*)&r1.x);
            float2 y1 = __half22float2(*(__half2*)&r1.y);
            float2 z0 = __half22float2(*(__half2*)&r2.x);
            float2 z1 = __half22float2(*(__half2*)&r2.y);
            float2 w0 = __half22float2(*(__half2*)&r3.x);
            float2 w1 = __half22float2(*(__half2*)&r3.y);
            s0 += x0.x + z0.x; s1 += x0.y + z0.y;
            s2 += x1.x + z1.x; s3 += x1.y + z1.y;
            u0 += y0.x + w0.x; u1 += y0.y + w0.y;
            u2 += y1.x + w1.x; u3 += y1.y + w1.y;
        }
        for (; e < end; e++) {
            int a = __ldg(&adj[e]);
            uint2 r0 = __ldg(&tv[(size_t)a * 32 + lane]);
            float2 x0 = __half22float2(*(__half2*)&r0.x);
            float2 x1 = __half22float2(*(__half2*)&r0.y);
            s0 += x0.x; s1 += x0.y; s2 += x1.x; s3 += x1.y;
        }
        float4 bv = __ldg(&((const float4*)b)[lane]);
        float o0 = fmaxf(fmaf(s0 + u0, d, bv.x), 0.f);
        float o1 = fmaxf(fmaf(s1 + u1, d, bv.y), 0.f);
        float o2 = fmaxf(fmaf(s2 + u2, d, bv.z), 0.f);
        float o3 = fmaxf(fmaf(s3 + u3, d, bv.w), 0.f);
        __half2 q0 = __floats2half2_rn(o0, o1);
        __half2 q1 = __floats2half2_rn(o2, o3);
        uint2 pk;
        pk.x = *(unsigned*)&q0;
        pk.y = *(unsigned*)&q1;
        ((uint2*)h)[(size_t)node * 32 + lane] = pk;
    } else {
        const uint32_t* tv = (const uint32_t*)t;  // 2 halfs; 32 per row
        uint32_t raw = __ldg(&tv[(size_t)node * 32 + lane]);  // self loop
        float2 f0 = __half22float2(*(__half2*)&raw);
        float s0 = f0.x, s1 = f0.y;
        float u0 = 0.f, u1 = 0.f;
        int e = beg;
        for (; e + 4 <= end; e += 4) {
            int a0 = __ldg(&adj[e]);
            int a1 = __ldg(&adj[e + 1]);
            int a2 = __ldg(&adj[e + 2]);
            int a3 = __ldg(&adj[e + 3]);
            uint32_t r0 = __ldg(&tv[(size_t)a0 * 32 + lane]);
            uint32_t r1 = __ldg(&tv[(size_t)a1 * 32 + lane]);
            uint32_t r2 = __ldg(&tv[(size_t)a2 * 32 + lane]);
            uint32_t r3 = __ldg(&tv[(size_t)a3 * 32 + lane]);
            float2 x0 = __half22float2(*(__half2*)&r0);
            float2 y0 = __half22float2(*(__half2*)&r1);
            float2 z0 = __half22float2(*(__half2*)&r2);
            float2 w0 = __half22float2(*(__half2*)&r3);
            s0 += x0.x + z0.x; s1 += x0.y + z0.y;
            u0 += y0.x + w0.x; u1 += y0.y + w0.y;
        }
        for (; e < end; e++) {
            int a = __ldg(&adj[e]);
            uint32_t r0 = __ldg(&tv[(size_t)a * 32 + lane]);
            float2 x0 = __half22float2(*(__half2*)&r0);
            s0 += x0.x; s1 += x0.y;
        }
        float2 bv = __ldg(&((const float2*)b)[lane]);
        float o0 = fmaxf(fmaf(s0 + u0, d, bv.x), 0.f);
        float o1 = fmaxf(fmaf(s1 + u1, d, bv.y), 0.f);
        __half2 q = __floats2half2_rn(o0, o1);
        ((uint32_t*)h)[(size_t)node * 32 + lane] = *(unsigned*)&q;
    }
}

// ---------------------------------------------------------------------------
// pooling: batch sorted -> segmented reduction. Block = 256 thr = 4 groups of
// 64 features; each group reduces a 64-node segment. fp16 h in, fp32 accum.
// ---------------------------------------------------------------------------
__global__ __launch_bounds__(256) void pool_kernel(
    const __half* __restrict__ h, const int* __restrict__ batch,
    float* __restrict__ sums, float* __restrict__ cnt, int N) {
    int grp = threadIdx.x >> 6;
    int f = threadIdx.x & 63;
    int start = blockIdx.x * 256 + grp * 64;
    if (start >= N) return;
    int end = min(start + 64, N);
    int g = batch[start];
    float s = 0.f, c = 0.f;
    for (int n = start; n < end; n++) {
        int bn = batch[n];
        if (bn != g) {
            atomicAdd(&sums[g * 64 + f], s);
            if (f == 0) atomicAdd(&cnt[g], c);
            s = 0.f; c = 0.f; g = bn;
        }
        s += __half2float(h[(size_t)n * 64 + f]);
        c += 1.f;
    }
    atomicAdd(&sums[g * 64 + f], s);
    if (f == 0) atomicAdd(&cnt[g], c);
}

__global__ void final_kernel(const float* __restrict__ sums, const float* __restrict__ cnt,
                             const float* __restrict__ Wl, const float* __restrict__ bl,
                             float* __restrict__ out) {
    int g = blockIdx.x * blockDim.x + threadIdx.x;
    if (g >= NG_GRAPHS) return;
    float c = fmaxf(cnt[g], 1.0f);
    float acc = 0.f;
#pragma unroll
    for (int f = 0; f < 64; f++) acc = fmaf(sums[g * 64 + f], Wl[f], acc);
    out[g] = acc / c + bl[0];
}

// ---------------------------------------------------------------------------
extern "C" void kernel_launch(void* const* d_in, const int* in_sizes, int n_in,
                              void* d_out, int out_size) {
    const float* x     = (const float*)d_in[0];
    const int*   ei    = (const int*)d_in[1];    // int32
    const int*   batch = (const int*)d_in[2];    // int32
    const float* W1 = (const float*)d_in[3];
    const float* b1 = (const float*)d_in[4];
    const float* W2 = (const float*)d_in[5];
    const float* b2 = (const float*)d_in[6];
    const float* W3 = (const float*)d_in[7];
    const float* b3 = (const float*)d_in[8];
    const float* Wl = (const float*)d_in[9];
    const float* bl = (const float*)d_in[10];
    float* out = (float*)d_out;

    const int N = in_sizes[0] / 3;
    const int E = in_sizes[1] / 2;
    const int* srcp = ei;
    const int* dstp = ei + E;

    float *xd, *dis, *sums, *gcnt;
    __half *t, *h;
    __nv_bfloat16 *bh2, *bl2, *bh3, *bl3;
    int *cnt, *offs, *cur, *adj, *bsum;
    cudaGetSymbolAddress((void**)&t, g_t);
    cudaGetSymbolAddress((void**)&h, g_h);
    cudaGetSymbolAddress((void**)&xd, g_xd);
    cudaGetSymbolAddress((void**)&bh2, g_bh2);
    cudaGetSymbolAddress((void**)&bl2, g_bl2);
    cudaGetSymbolAddress((void**)&bh3, g_bh3);
    cudaGetSymbolAddress((void**)&bl3, g_bl3);
    cudaGetSymbolAddress((void**)&dis, g_dis);
    cudaGetSymbolAddress((void**)&cnt, g_cnt);
    cudaGetSymbolAddress((void**)&offs, g_offs);
    cudaGetSymbolAddress((void**)&cur, g_cur);
    cudaGetSymbolAddress((void**)&adj, g_adj);
    cudaGetSymbolAddress((void**)&bsum, g_bsum);
    cudaGetSymbolAddress((void**)&sums, g_sums);
    cudaGetSymbolAddress((void**)&gcnt, g_gcnt);

    // smem: (128 A rows hi+lo + F B rows hi+lo) x LDH halfs
    const int SMEM128 = (2 * 128 + 2 * 128) * LDH * 2;  // 73,728 B
    const int SMEM64  = (2 * 128 + 2 * 64) * LDH * 2;   // 55,296 B
    cudaFuncSetAttribute(gemm_mma_kernel<128>,
                         cudaFuncAttributeMaxDynamicSharedMemorySize, SMEM128);
    cudaFuncSetAttribute(gemm_mma_kernel<64>,
                         cudaFuncAttributeMaxDynamicSharedMemorySize, SMEM64);

    const int nB = (N + 255) / 256;
    const int eB = (E + 255) / 256;
    const int NB_SCAN = (N + SCAN_B - 1) / SCAN_B;
    const int wB = (N * 32 + 255) / 256;      // warp-per-node grids
    const int gB = (N + 127) / 128;           // gemm grids
    const int fpB = (E + 128 * 128 + 64 * 128 + 255) / 256;

    // --- CSR build + prep (cnt is zero at entry: zero-init on call 1, ---
    // --- self-cleared by scan_add on every call)                      ---
    count_kernel<<<eB, 256>>>(dstp, cnt, sums, gcnt, E);
    scan_block_kernel<<<NB_SCAN, SCAN_B>>>(cnt, offs, bsum, N);
    scan_add_kernel<<<nB, 256>>>(offs, bsum, cur, cnt, x, dis, xd, N, E);
    fill_prep_kernel<<<fpB, 256>>>(srcp, dstp, cur, adj, E,
                                   W2, W3, bh2, bl2, bh3, bl3);

    // --- layer 1 (3 -> 128): fused aggregate + transform ---
    l1_fused_kernel<<<wB, 256>>>(offs, adj, xd, W1, dis, b1, h, N);

    // --- layer 2 (128 -> 128) ---
    gemm_mma_kernel<128><<<gB, 256, SMEM128>>>(h, bh2, bl2, dis, t, N);
    gather_kernel<128><<<wB, 256>>>(offs, adj, t, dis, b2, h, N);

    // --- layer 3 (128 -> 64) ---
    gemm_mma_kernel<64><<<gB, 256, SMEM64>>>(h, bh3, bl3, dis, t, N);
    gather_kernel<64><<<wB, 256>>>(offs, adj, t, dis, b3, h, N);

    // --- pooling + final linear ---
    pool_kernel<<<nB, 256>>>(h, batch, sums, gcnt, N);
    final_kernel<<<2, 256>>>(sums, gcnt, Wl, bl, out);
}

// round 12
// speedup vs baseline: 2.2069x; 1.0065x over previous
#include <cuda_runtime.h>
#include <cuda_bf16.h>
#include <cuda_fp16.h>
#include <cstdint>

#define MAXN 100000
#define MAXE 600000
#define NG_GRAPHS 512
#define SCAN_B 1024

// Scratch (static device globals; allocation-free).
// NOTE: g_cnt relies on (a) CUDA zero-init of device globals for the first
// call, (b) scan_add_kernel re-zeroing it at the end of every call.
__device__ __align__(16) __half g_t[MAXN * 128];   // fp16 GEMM output (gather payload)
__device__ __align__(16) __half g_h[MAXN * 128];   // fp16 activations
__device__ __align__(16) float g_xd[MAXN * 4];     // x * dis, padded float4
__device__ __align__(16) __nv_bfloat16 g_bh2[128 * 128];  // W2^T hi (n-major [n][k])
__device__ __align__(16) __nv_bfloat16 g_bl2[128 * 128];  // W2^T lo
__device__ __align__(16) __nv_bfloat16 g_bh3[64 * 128];   // W3^T hi
__device__ __align__(16) __nv_bfloat16 g_bl3[64 * 128];   // W3^T lo
__device__ __align__(16) float g_dis[MAXN];
__device__ __align__(16) int   g_cnt[MAXN];
__device__ __align__(16) int   g_offs[MAXN + 1];
__device__ __align__(16) int   g_slot[MAXE];       // within-node slot per edge
__device__ __align__(16) int   g_adj[MAXE];
__device__ __align__(16) int   g_bsum[128];
__device__ __align__(16) float g_sums[NG_GRAPHS * 64];
__device__ __align__(16) float g_gcnt[NG_GRAPHS];

// ---------------------------------------------------------------------------
// count in-degrees, 4 edges/thread (MLP=4); atomic return value IS the slot.
// Also zeroes pooling buffers.
// ---------------------------------------------------------------------------
__global__ void count_kernel(const int* __restrict__ dst, int* cnt, int* slot,
                             float* sums, float* gcnt, int E) {
    int i = blockIdx.x * blockDim.x + threadIdx.x;
    int e = i * 4;
    if (e + 4 <= E) {
        int4 d = *(const int4*)(dst + e);
        int4 s;
        s.x = atomicAdd(&cnt[d.x], 1);
        s.y = atomicAdd(&cnt[d.y], 1);
        s.z = atomicAdd(&cnt[d.z], 1);
        s.w = atomicAdd(&cnt[d.w], 1);
        *(int4*)(slot + e) = s;
    } else {
        for (int j = e; j < E; j++) slot[j] = atomicAdd(&cnt[dst[j]], 1);
    }
    if (i < NG_GRAPHS * 64) sums[i] = 0.f;
    if (i < NG_GRAPHS) gcnt[i] = 0.f;
}

__global__ __launch_bounds__(SCAN_B) void scan_block_kernel(
    const int* __restrict__ cnt, int* offs, int* bsum, int N) {
    __shared__ int sh[SCAN_B];
    int t = threadIdx.x;
    int i = blockIdx.x * SCAN_B + t;
    int v = (i < N) ? cnt[i] : 0;
    sh[t] = v;
    __syncthreads();
#pragma unroll
    for (int off = 1; off < SCAN_B; off <<= 1) {
        int add = (t >= off) ? sh[t - off] : 0;
        __syncthreads();
        sh[t] += add;
        __syncthreads();
    }
    if (i < N) offs[i] = sh[t] - v;  // exclusive within tile
    if (t == SCAN_B - 1) bsum[blockIdx.x] = sh[t];  // tile total (raw)
}

// apply top-level scan (computed in-block over <=98 tile totals), finalize
// offs, compute dis and xd = x*dis, and self-clear cnt for the next call.
__global__ __launch_bounds__(256) void scan_add_kernel(
    int* offs, const int* __restrict__ bsum, int* cnt,
    const float* __restrict__ x, float* dis, float* xd, int N, int E) {
    __shared__ int base_sh;
    int tile = blockIdx.x >> 2;  // 256-thread block lies inside one 1024 tile
    if (threadIdx.x < 32) {
        int s = 0;
        for (int j = threadIdx.x; j < tile; j += 32) s += bsum[j];
#pragma unroll
        for (int o = 16; o; o >>= 1) s += __shfl_down_sync(0xFFFFFFFFu, s, o);
        if (threadIdx.x == 0) base_sh = s;
    }
    __syncthreads();
    int i = blockIdx.x * 256 + threadIdx.x;
    if (i < N) {
        offs[i] += base_sh;
        float d = rsqrtf((float)cnt[i] + 1.0f);  // +1 self loop
        cnt[i] = 0;                              // reset for next call
        dis[i] = d;
        float4 v;
        v.x = x[i * 3 + 0] * d;
        v.y = x[i * 3 + 1] * d;
        v.z = x[i * 3 + 2] * d;
        v.w = 0.f;
        *(float4*)(xd + i * 4) = v;
    }
    if (i == 0) offs[N] = E;
}

// ---------------------------------------------------------------------------
// fused: CSR fill (atomic-free scatter, 4 edges/thread) + W2/W3 prep
// ---------------------------------------------------------------------------
__global__ void fill_prep_kernel(const int* __restrict__ src, const int* __restrict__ dst,
                                 const int* __restrict__ offs, const int* __restrict__ slot,
                                 int* adj, int EQ, int E,
                                 const float* __restrict__ W2, const float* __restrict__ W3,
                                 __nv_bfloat16* bh2, __nv_bfloat16* bl2,
                                 __nv_bfloat16* bh3, __nv_bfloat16* bl3) {
    int i = blockIdx.x * blockDim.x + threadIdx.x;
    if (i < EQ) {
        int e = i * 4;
        if (e + 4 <= E) {
            int4 d = *(const int4*)(dst + e);
            int4 s = *(const int4*)(src + e);
            int4 sl = *(const int4*)(slot + e);
            adj[__ldg(&offs[d.x]) + sl.x] = s.x;
            adj[__ldg(&offs[d.y]) + sl.y] = s.y;
            adj[__ldg(&offs[d.z]) + sl.z] = s.z;
            adj[__ldg(&offs[d.w]) + sl.w] = s.w;
        } else {
            for (int j = e; j < E; j++)
                adj[__ldg(&offs[dst[j]]) + slot[j]] = src[j];
        }
        return;
    }
    int k = i - EQ;
    if (k < 128 * 128) {
        int kk = k >> 7, n = k & 127;            // coalesced read of W2 row kk
        float w = W2[kk * 128 + n];
        __nv_bfloat16 hi = __float2bfloat16_rn(w);
        __nv_bfloat16 lo = __float2bfloat16_rn(w - __bfloat162float(hi));
        bh2[n * 128 + kk] = hi;                  // scattered store
        bl2[n * 128 + kk] = lo;
    } else if (k < 128 * 128 + 64 * 128) {
        int j = k - 128 * 128;
        int kk = j >> 6, n = j & 63;             // coalesced read of W3 row kk
        float w = W3[kk * 64 + n];
        __nv_bfloat16 hi = __float2bfloat16_rn(w);
        __nv_bfloat16 lo = __float2bfloat16_rn(w - __bfloat162float(hi));
        bh3[n * 128 + kk] = hi;
        bl3[n * 128 + kk] = lo;
    }
}

// ---------------------------------------------------------------------------
// fused layer 1: warp per node.
//   z = xd[n] + sum_{s in adj(n)} xd[s]   (lane-strided + shfl reduce)
//   h[n] = fp16( relu(dis[n] * (z @ W1) + b1) )
// ---------------------------------------------------------------------------
__global__ __launch_bounds__(256) void l1_fused_kernel(
    const int* __restrict__ offs, const int* __restrict__ adj,
    const float* __restrict__ xd, const float* __restrict__ W1,
    const float* __restrict__ dis, const float* __restrict__ b1,
    __half* __restrict__ h, int N) {
    __shared__ float ws[3 * 128];
    __shared__ float bs[128];
    for (int i = threadIdx.x; i < 384; i += blockDim.x) ws[i] = W1[i];
    for (int i = threadIdx.x; i < 128; i += blockDim.x) bs[i] = b1[i];
    __syncthreads();
    int node = (blockIdx.x * 256 + threadIdx.x) >> 5;
    int lane = threadIdx.x & 31;
    if (node >= N) return;
    int beg = offs[node];
    int end = offs[node + 1];
    const float4* xv = (const float4*)xd;
    float sx = 0.f, sy = 0.f, sz = 0.f;
    for (int e = beg + lane; e < end; e += 32) {
        int a = __ldg(&adj[e]);
        float4 v = __ldg(&xv[a]);
        sx += v.x; sy += v.y; sz += v.z;
    }
#pragma unroll
    for (int o = 16; o; o >>= 1) {
        sx += __shfl_xor_sync(0xFFFFFFFFu, sx, o);
        sy += __shfl_xor_sync(0xFFFFFFFFu, sy, o);
        sz += __shfl_xor_sync(0xFFFFFFFFu, sz, o);
    }
    float4 self = __ldg(&xv[node]);
    sx += self.x; sy += self.y; sz += self.z;
    float d = dis[node];
    int f = lane * 4;
    float o0 = fmaxf(fmaf(sx * ws[f + 0] + sy * ws[128 + f + 0] + sz * ws[256 + f + 0], d, bs[f + 0]), 0.f);
    float o1 = fmaxf(fmaf(sx * ws[f + 1] + sy * ws[128 + f + 1] + sz * ws[256 + f + 1], d, bs[f + 1]), 0.f);
    float o2 = fmaxf(fmaf(sx * ws[f + 2] + sy * ws[128 + f + 2] + sz * ws[256 + f + 2], d, bs[f + 2]), 0.f);
    float o3 = fmaxf(fmaf(sx * ws[f + 3] + sy * ws[128 + f + 3] + sz * ws[256 + f + 3], d, bs[f + 3]), 0.f);
    __half2 q0 = __floats2half2_rn(o0, o1);
    __half2 q1 = __floats2half2_rn(o2, o3);
    uint2 pk;
    pk.x = *(unsigned*)&q0;
    pk.y = *(unsigned*)&q1;
    *(uint2*)(h + (size_t)node * 128 + f) = pk;
}

// ---------------------------------------------------------------------------
// bf16x3 tensor-core GEMM via mma.sync.m16n8k16 (legacy HMMA, sm_103-safe):
//   out[n] = fp16( (A[n] @ W) * dis[n] ),  D = Ahi*Bhi + Alo*Bhi + Ahi*Blo.
// A input fp16 (bf16 hi/lo split is EXACT for fp16 values); out fp16.
// Block = 256 thr (8 warps), tile = 128 rows x F. K staged in 2 chunks of 64.
// ---------------------------------------------------------------------------
#define LDH 72  // halfs per smem row (64 + 8 pad)

template <int F>
__global__ __launch_bounds__(256) void gemm_mma_kernel(
    const __half* __restrict__ A, const __nv_bfloat16* __restrict__ Bhg,
    const __nv_bfloat16* __restrict__ Blg, const float* __restrict__ dis,
    __half* __restrict__ out, int N) {
    extern __shared__ __align__(16) __nv_bfloat16 smh[];
    __nv_bfloat16* Ah = smh;             // 128 x LDH
    __nv_bfloat16* Al = Ah + 128 * LDH;  // 128 x LDH
    __nv_bfloat16* Bh = Al + 128 * LDH;  // F x LDH
    __nv_bfloat16* Bl = Bh + F * LDH;    // F x LDH

    const int tid = threadIdx.x;
    const int warp = tid >> 5;
    const int lane = tid & 31;
    const int g = lane >> 2;   // 0..7
    const int tg = lane & 3;   // 0..3
    const int n0 = blockIdx.x * 128;

    constexpr int NT = F / 8;
    float acc[NT][4];
#pragma unroll
    for (int i = 0; i < NT; i++) {
        acc[i][0] = acc[i][1] = acc[i][2] = acc[i][3] = 0.f;
    }

    for (int kc = 0; kc < 128; kc += 64) {
        __syncthreads();  // protect smem from previous chunk's readers
        // stage A chunk [128 x 64] fp16 -> bf16 hi/lo split (exact)
        for (int i = tid; i < 128 * 8; i += 256) {
            int r = i >> 3, c8 = i & 7;           // 8 halfs per thread-iter
            uint4 raw = make_uint4(0u, 0u, 0u, 0u);
            int n = n0 + r;
            if (n < N) raw = *(const uint4*)(A + (size_t)n * 128 + kc + c8 * 8);
            const __half2* hp = (const __half2*)&raw;
            uint4 hu, lu;
            uint32_t* hw = (uint32_t*)&hu;
            uint32_t* lw = (uint32_t*)&lu;
#pragma unroll
            for (int q = 0; q < 4; q++) {
                float2 fv = __half22float2(hp[q]);
                __nv_bfloat16 h0 = __float2bfloat16_rn(fv.x);
                __nv_bfloat16 h1 = __float2bfloat16_rn(fv.y);
                __nv_bfloat162 hh = {h0, h1};
                __nv_bfloat162 ll = {__float2bfloat16_rn(fv.x - __bfloat162float(h0)),
                                     __float2bfloat16_rn(fv.y - __bfloat162float(h1))};
                hw[q] = *(uint32_t*)&hh;
                lw[q] = *(uint32_t*)&ll;
            }
            *(uint4*)(Ah + r * LDH + c8 * 8) = hu;
            *(uint4*)(Al + r * LDH + c8 * 8) = lu;
        }
        // stage B chunk [F x 64] (already bf16 hi/lo in global, n-major)
        for (int i = tid; i < F * 8; i += 256) {
            int r = i >> 3, c8 = i & 7;
            *(uint4*)(Bh + r * LDH + c8 * 8) = *(const uint4*)(Bhg + r * 128 + kc + c8 * 8);
            *(uint4*)(Bl + r * LDH + c8 * 8) = *(const uint4*)(Blg + r * 128 + kc + c8 * 8);
        }
        __syncthreads();

        const __nv_bfloat16* ar0 = Ah + (warp * 16 + g) * LDH + 2 * tg;
        const __nv_bfloat16* al0 = Al + (warp * 16 + g) * LDH + 2 * tg;
#pragma unroll
        for (int ks = 0; ks < 4; ks++) {
            const int ko = ks * 16;
            uint32_t ah0 = *(const uint32_t*)(ar0 + ko);
            uint32_t ah1 = *(const uint32_t*)(ar0 + 8 * LDH + ko);
            uint32_t ah2 = *(const uint32_t*)(ar0 + ko + 8);
            uint32_t ah3 = *(const uint32_t*)(ar0 + 8 * LDH + ko + 8);
            uint32_t aw0 = *(const uint32_t*)(al0 + ko);
            uint32_t aw1 = *(const uint32_t*)(al0 + 8 * LDH + ko);
            uint32_t aw2 = *(const uint32_t*)(al0 + ko + 8);
            uint32_t aw3 = *(const uint32_t*)(al0 + 8 * LDH + ko + 8);
#pragma unroll
            for (int nt = 0; nt < NT; nt++) {
                const __nv_bfloat16* bhr = Bh + (nt * 8 + g) * LDH + 2 * tg + ko;
                const __nv_bfloat16* blr = Bl + (nt * 8 + g) * LDH + 2 * tg + ko;
                uint32_t bh0 = *(const uint32_t*)bhr;
                uint32_t bh1 = *(const uint32_t*)(bhr + 8);
                uint32_t bl0 = *(const uint32_t*)blr;
                uint32_t bl1 = *(const uint32_t*)(blr + 8);
                asm volatile(
                    "mma.sync.aligned.m16n8k16.row.col.f32.bf16.bf16.f32 "
                    "{%0,%1,%2,%3}, {%4,%5,%6,%7}, {%8,%9}, {%0,%1,%2,%3};"
                    : "+f"(acc[nt][0]), "+f"(acc[nt][1]), "+f"(acc[nt][2]), "+f"(acc[nt][3])
                    : "r"(ah0), "r"(ah1), "r"(ah2), "r"(ah3), "r"(bh0), "r"(bh1));
                asm volatile(
                    "mma.sync.aligned.m16n8k16.row.col.f32.bf16.bf16.f32 "
                    "{%0,%1,%2,%3}, {%4,%5,%6,%7}, {%8,%9}, {%0,%1,%2,%3};"
                    : "+f"(acc[nt][0]), "+f"(acc[nt][1]), "+f"(acc[nt][2]), "+f"(acc[nt][3])
                    : "r"(aw0), "r"(aw1), "r"(aw2), "r"(aw3), "r"(bh0), "r"(bh1));
                asm volatile(
                    "mma.sync.aligned.m16n8k16.row.col.f32.bf16.bf16.f32 "
                    "{%0,%1,%2,%3}, {%4,%5,%6,%7}, {%8,%9}, {%0,%1,%2,%3};"
                    : "+f"(acc[nt][0]), "+f"(acc[nt][1]), "+f"(acc[nt][2]), "+f"(acc[nt][3])
                    : "r"(ah0), "r"(ah1), "r"(ah2), "r"(ah3), "r"(bl0), "r"(bl1));
            }
        }
    }

    // epilogue: x dis, fp16 store. c0,c1 = row g cols 2tg,2tg+1; c2,c3 = g+8.
    int m0 = n0 + warp * 16 + g;
    int m1 = m0 + 8;
    float d0 = (m0 < N) ? dis[m0] : 0.f;
    float d1 = (m1 < N) ? dis[m1] : 0.f;
#pragma unroll
    for (int nt = 0; nt < NT; nt++) {
        if (m0 < N) {
            __half2 o = __floats2half2_rn(acc[nt][0] * d0, acc[nt][1] * d0);
            *(__half2*)(out + (size_t)m0 * F + nt * 8 + tg * 2) = o;
        }
        if (m1 < N) {
            __half2 o = __floats2half2_rn(acc[nt][2] * d1, acc[nt][3] * d1);
            *(__half2*)(out + (size_t)m1 * F + nt * 8 + tg * 2) = o;
        }
    }
}

// ---------------------------------------------------------------------------
// CSR gather + epilogue: h[d] = fp16(relu(dis[d]*(sum t[s] + t[d]) + b))
// One warp per dst node; fp16 payload, fp32 accumulation, fp16 h out.
// ---------------------------------------------------------------------------
template <int F>
__global__ __launch_bounds__(256) void gather_kernel(
    const int* __restrict__ offs, const int* __restrict__ adj,
    const __half* __restrict__ t, const float* __restrict__ dis,
    const float* __restrict__ b, __half* __restrict__ h, int N) {
    int node = (blockIdx.x * 256 + threadIdx.x) >> 5;
    int lane = threadIdx.x & 31;
    if (node >= N) return;
    int beg = offs[node];
    int end = offs[node + 1];
    float d = dis[node];
    if constexpr (F == 128) {
        const uint2* tv = (const uint2*)t;  // 4 halfs per elem; 32 per row
        uint2 raw = __ldg(&tv[(size_t)node * 32 + lane]);  // self loop
        float2 f0 = __half22float2(*(__half2*)&raw.x);
        float2 f1 = __half22float2(*(__half2*)&raw.y);
        float s0 = f0.x, s1 = f0.y, s2 = f1.x, s3 = f1.y;
        float u0 = 0.f, u1 = 0.f, u2 = 0.f, u3 = 0.f;
        int e = beg;
        for (; e + 4 <= end; e += 4) {
            int a0 = __ldg(&adj[e]);
            int a1 = __ldg(&adj[e + 1]);
            int a2 = __ldg(&adj[e + 2]);
            int a3 = __ldg(&adj[e + 3]);
            uint2 r0 = __ldg(&tv[(size_t)a0 * 32 + lane]);
            uint2 r1 = __ldg(&tv[(size_t)a1 * 32 + lane]);
            uint2 r2 = __ldg(&tv[(size_t)a2 * 32 + lane]);
            uint2 r3 = __ldg(&tv[(size_t)a3 * 32 + lane]);
            float2 x0 = __half22float2(*(__half2*)&r0.x);
            float2 x1 = __half22float2(*(__half2*)&r0.y);
            float2 y0 = __half22float2(*(__half2*)&r1.x);
            float2 y1 = __half22float2(*(__half2*)&r1.y);
            float2 z0 = __half22float2(*(__half2*)&r2.x);
            float2 z1 = __half22float2(*(__half2*)&r2.y);
            float2 w0 = __half22float2(*(__half2*)&r3.x);
            float2 w1 = __half22float2(*(__half2*)&r3.y);
            s0 += x0.x + z0.x; s1 += x0.y + z0.y;
            s2 += x1.x + z1.x; s3 += x1.y + z1.y;
            u0 += y0.x + w0.x; u1 += y0.y + w0.y;
            u2 += y1.x + w1.x; u3 += y1.y + w1.y;
        }
        for (; e < end; e++) {
            int a = __ldg(&adj[e]);
            uint2 r0 = __ldg(&tv[(size_t)a * 32 + lane]);
            float2 x0 = __half22float2(*(__half2*)&r0.x);
            float2 x1 = __half22float2(*(__half2*)&r0.y);
            s0 += x0.x; s1 += x0.y; s2 += x1.x; s3 += x1.y;
        }
        float4 bv = __ldg(&((const float4*)b)[lane]);
        float o0 = fmaxf(fmaf(s0 + u0, d, bv.x), 0.f);
        float o1 = fmaxf(fmaf(s1 + u1, d, bv.y), 0.f);
        float o2 = fmaxf(fmaf(s2 + u2, d, bv.z), 0.f);
        float o3 = fmaxf(fmaf(s3 + u3, d, bv.w), 0.f);
        __half2 q0 = __floats2half2_rn(o0, o1);
        __half2 q1 = __floats2half2_rn(o2, o3);
        uint2 pk;
        pk.x = *(unsigned*)&q0;
        pk.y = *(unsigned*)&q1;
        ((uint2*)h)[(size_t)node * 32 + lane] = pk;
    } else {
        const uint32_t* tv = (const uint32_t*)t;  // 2 halfs; 32 per row
        uint32_t raw = __ldg(&tv[(size_t)node * 32 + lane]);  // self loop
        float2 f0 = __half22float2(*(__half2*)&raw);
        float s0 = f0.x, s1 = f0.y;
        float u0 = 0.f, u1 = 0.f;
        int e = beg;
        for (; e + 4 <= end; e += 4) {
            int a0 = __ldg(&adj[e]);
            int a1 = __ldg(&adj[e + 1]);
            int a2 = __ldg(&adj[e + 2]);
            int a3 = __ldg(&adj[e + 3]);
            uint32_t r0 = __ldg(&tv[(size_t)a0 * 32 + lane]);
            uint32_t r1 = __ldg(&tv[(size_t)a1 * 32 + lane]);
            uint32_t r2 = __ldg(&tv[(size_t)a2 * 32 + lane]);
            uint32_t r3 = __ldg(&tv[(size_t)a3 * 32 + lane]);
            float2 x0 = __half22float2(*(__half2*)&r0);
            float2 y0 = __half22float2(*(__half2*)&r1);
            float2 z0 = __half22float2(*(__half2*)&r2);
            float2 w0 = __half22float2(*(__half2*)&r3);
            s0 += x0.x + z0.x; s1 += x0.y + z0.y;
            u0 += y0.x + w0.x; u1 += y0.y + w0.y;
        }
        for (; e < end; e++) {
            int a = __ldg(&adj[e]);
            uint32_t r0 = __ldg(&tv[(size_t)a * 32 + lane]);
            float2 x0 = __half22float2(*(__half2*)&r0);
            s0 += x0.x; s1 += x0.y;
        }
        float2 bv = __ldg(&((const float2*)b)[lane]);
        float o0 = fmaxf(fmaf(s0 + u0, d, bv.x), 0.f);
        float o1 = fmaxf(fmaf(s1 + u1, d, bv.y), 0.f);
        __half2 q = __floats2half2_rn(o0, o1);
        ((uint32_t*)h)[(size_t)node * 32 + lane] = *(unsigned*)&q;
    }
}

// ---------------------------------------------------------------------------
// pooling: batch sorted -> segmented reduction. Block = 256 thr = 4 groups of
// 64 features; each group reduces a 64-node segment. fp16 h in, fp32 accum.
// ---------------------------------------------------------------------------
__global__ __launch_bounds__(256) void pool_kernel(
    const __half* __restrict__ h, const int* __restrict__ batch,
    float* __restrict__ sums, float* __restrict__ cnt, int N) {
    int grp = threadIdx.x >> 6;
    int f = threadIdx.x & 63;
    int start = blockIdx.x * 256 + grp * 64;
    if (start >= N) return;
    int end = min(start + 64, N);
    int g = batch[start];
    float s = 0.f, c = 0.f;
    for (int n = start; n < end; n++) {
        int bn = batch[n];
        if (bn != g) {
            atomicAdd(&sums[g * 64 + f], s);
            if (f == 0) atomicAdd(&cnt[g], c);
            s = 0.f; c = 0.f; g = bn;
        }
        s += __half2float(h[(size_t)n * 64 + f]);
        c += 1.f;
    }
    atomicAdd(&sums[g * 64 + f], s);
    if (f == 0) atomicAdd(&cnt[g], c);
}

__global__ void final_kernel(const float* __restrict__ sums, const float* __restrict__ cnt,
                             const float* __restrict__ Wl, const float* __restrict__ bl,
                             float* __restrict__ out) {
    int g = blockIdx.x * blockDim.x + threadIdx.x;
    if (g >= NG_GRAPHS) return;
    float c = fmaxf(cnt[g], 1.0f);
    float acc = 0.f;
#pragma unroll
    for (int f = 0; f < 64; f++) acc = fmaf(sums[g * 64 + f], Wl[f], acc);
    out[g] = acc / c + bl[0];
}

// ---------------------------------------------------------------------------
extern "C" void kernel_launch(void* const* d_in, const int* in_sizes, int n_in,
                              void* d_out, int out_size) {
    const float* x     = (const float*)d_in[0];
    const int*   ei    = (const int*)d_in[1];    // int32
    const int*   batch = (const int*)d_in[2];    // int32
    const float* W1 = (const float*)d_in[3];
    const float* b1 = (const float*)d_in[4];
    const float* W2 = (const float*)d_in[5];
    const float* b2 = (const float*)d_in[6];
    const float* W3 = (const float*)d_in[7];
    const float* b3 = (const float*)d_in[8];
    const float* Wl = (const float*)d_in[9];
    const float* bl = (const float*)d_in[10];
    float* out = (float*)d_out;

    const int N = in_sizes[0] / 3;
    const int E = in_sizes[1] / 2;
    const int* srcp = ei;
    const int* dstp = ei + E;

    float *xd, *dis, *sums, *gcnt;
    __half *t, *h;
    __nv_bfloat16 *bh2, *bl2, *bh3, *bl3;
    int *cnt, *offs, *slot, *adj, *bsum;
    cudaGetSymbolAddress((void**)&t, g_t);
    cudaGetSymbolAddress((void**)&h, g_h);
    cudaGetSymbolAddress((void**)&xd, g_xd);
    cudaGetSymbolAddress((void**)&bh2, g_bh2);
    cudaGetSymbolAddress((void**)&bl2, g_bl2);
    cudaGetSymbolAddress((void**)&bh3, g_bh3);
    cudaGetSymbolAddress((void**)&bl3, g_bl3);
    cudaGetSymbolAddress((void**)&dis, g_dis);
    cudaGetSymbolAddress((void**)&cnt, g_cnt);
    cudaGetSymbolAddress((void**)&offs, g_offs);
    cudaGetSymbolAddress((void**)&slot, g_slot);
    cudaGetSymbolAddress((void**)&adj, g_adj);
    cudaGetSymbolAddress((void**)&bsum, g_bsum);
    cudaGetSymbolAddress((void**)&sums, g_sums);
    cudaGetSymbolAddress((void**)&gcnt, g_gcnt);

    // smem: (128 A rows hi+lo + F B rows hi+lo) x LDH halfs
    const int SMEM128 = (2 * 128 + 2 * 128) * LDH * 2;  // 73,728 B
    const int SMEM64  = (2 * 128 + 2 * 64) * LDH * 2;   // 55,296 B
    cudaFuncSetAttribute(gemm_mma_kernel<128>,
                         cudaFuncAttributeMaxDynamicSharedMemorySize, SMEM128);
    cudaFuncSetAttribute(gemm_mma_kernel<64>,
                         cudaFuncAttributeMaxDynamicSharedMemorySize, SMEM64);

    const int nB = (N + 255) / 256;
    const int NB_SCAN = (N + SCAN_B - 1) / SCAN_B;
    const int wB = (N * 32 + 255) / 256;      // warp-per-node grids
    const int gB = (N + 127) / 128;           // gemm grids
    const int EQ = (E + 3) / 4;               // edge quads
    const int cntB = (EQ + 255) / 256;        // count grid (covers 32768 zeroing: EQ=150000)
    const int fpB = (EQ + 128 * 128 + 64 * 128 + 255) / 256;

    // --- CSR build + prep (cnt is zero at entry: zero-init on call 1, ---
    // --- self-cleared by scan_add on every call)                      ---
    count_kernel<<<cntB, 256>>>(dstp, cnt, slot, sums, gcnt, E);
    scan_block_kernel<<<NB_SCAN, SCAN_B>>>(cnt, offs, bsum, N);
    scan_add_kernel<<<nB, 256>>>(offs, bsum, cnt, x, dis, xd, N, E);
    fill_prep_kernel<<<fpB, 256>>>(srcp, dstp, offs, slot, adj, EQ, E,
                                   W2, W3, bh2, bl2, bh3, bl3);

    // --- layer 1 (3 -> 128): fused aggregate + transform ---
    l1_fused_kernel<<<wB, 256>>>(offs, adj, xd, W1, dis, b1, h, N);

    // --- layer 2 (128 -> 128) ---
    gemm_mma_kernel<128><<<gB, 256, SMEM128>>>(h, bh2, bl2, dis, t, N);
    gather_kernel<128><<<wB, 256>>>(offs, adj, t, dis, b2, h, N);

    // --- layer 3 (128 -> 64) ---
    gemm_mma_kernel<64><<<gB, 256, SMEM64>>>(h, bh3, bl3, dis, t, N);
    gather_kernel<64><<<wB, 256>>>(offs, adj, t, dis, b3, h, N);

    // --- pooling + final linear ---
    pool_kernel<<<nB, 256>>>(h, batch, sums, gcnt, N);
    final_kernel<<<2, 256>>>(sums, gcnt, Wl, bl, out);
}